// round 11
// baseline (speedup 1.0000x reference)
#include <cuda_runtime.h>

#define NN      50000
#define EE      800000
#define INDIM   128
#define D       64
#define H       4
#define NR      20
#define NB      8
#define STCOLS  160
#define W1COLS  320          // 64 (z) + 256 (self)
#define WSTLD   192          // Wst stride (160 cols padded to 3x64)

// ---- static scratch (no allocation allowed) ----
__device__ __align__(16) float g_z[NN * D];              // 12.8 MB
__device__ __align__(16) float g_st[NN * STCOLS];        // 32 MB
__device__ __align__(16) float g_W1[INDIM * W1COLS];     // 160 KB
__device__ __align__(16) float g_Wst[D * WSTLD];         // 48 KB
__device__ int g_deg[NN];
__device__ int g_rowptr[NN + 1];
__device__ int g_cursor[NN];
__device__ unsigned g_csr[EE];

// packed fp32x2 FMA: d = a*b + d (Blackwell)
#define FMA_F32X2(d, a, b) \
    asm("fma.rn.f32x2 %0, %1, %2, %0;" : "+l"(d) : "l"(a), "l"(b))
#define BCAST_F32X2(d, s) \
    asm("mov.b64 %0, {%1, %1};" : "=l"(d) : "f"(s))

// ---------------------------------------------------------------------------
// Wst[c][jj]: basis-combined attention weights (src part jj<80, dst part >=80)
// ---------------------------------------------------------------------------
__global__ void build_wst_kernel(const float* __restrict__ w_comp,
                                 const float* __restrict__ aw) {
    int idx = blockIdx.x * blockDim.x + threadIdx.x;
    if (idx >= D * WSTLD) return;
    int c  = idx / WSTLD;
    int jj = idx % WSTLD;
    if (jj >= STCOLS) { g_Wst[idx] = 0.f; return; }
    int r, hh, cc;
    if (jj < 80) { r = jj >> 2; hh = jj & 3; cc = c; }
    else         { int j2 = jj - 80; r = j2 >> 2; hh = j2 & 3; cc = c + D; }
    float acc = 0.f;
#pragma unroll
    for (int b = 0; b < NB; b++)
        acc += w_comp[r * NB + b] * aw[b * (2 * D * H) + cc * H + hh];
    g_Wst[idx] = acc;
}

// W1[k][j]: j<64 -> fc_w^T ; j in [64,320) -> self_fc_w^T
__global__ void build_w1_kernel(const float* __restrict__ fc_w,
                                const float* __restrict__ self_fc_w) {
    int idx = blockIdx.x * blockDim.x + threadIdx.x;
    if (idx >= INDIM * W1COLS) return;
    int k = idx / W1COLS;
    int j = idx % W1COLS;
    g_W1[idx] = (j < D) ? fc_w[j * INDIM + k] : self_fc_w[(j - D) * INDIM + k];
}

// ---------------------------------------------------------------------------
// SGEMM: BM=128, BN=64, BK=16, 256 thr, 8x4 microtile as f32x2 row-pairs.
// Double-buffered smem + register prefetch; one __syncthreads per k-iter.
// ---------------------------------------------------------------------------
#define BM 128
#define BN 64
#define BK 16

// GEMM1: C[N,320] = h[N,128] @ W1[128,320]; cols [0,64)->g_z, rest->d_out
__global__ __launch_bounds__(256) void gemm1_kernel(const float* __restrict__ A,
                                                    float* __restrict__ out) {
    __shared__ __align__(16) float As[2][BK][BM + 4];
    __shared__ __align__(16) float Bs[2][BK][BN];
    const int tid = threadIdx.x;
    const int tx = tid & 15;
    const int ty = tid >> 4;
    const int rowBase = blockIdx.y * BM;
    const int colBase = blockIdx.x * BN;
    const int aRow = tid >> 1;
    const int aK   = (tid & 1) << 3;
    const int bK   = tid >> 4;
    const int bCol = (tid & 15) << 2;
    const int gr   = rowBase + aRow;
    const bool aOk = (gr < NN);
    const float* aBase = A + (size_t)(aOk ? gr : 0) * INDIM + aK;
    const float* bBase = g_W1 + (size_t)bK * W1COLS + colBase + bCol;
    const int NIT = INDIM / BK;   // 8

    unsigned long long acc2[4][4];
#pragma unroll
    for (int i = 0; i < 4; i++)
#pragma unroll
        for (int j = 0; j < 4; j++) acc2[i][j] = 0ull;

    // prologue: tile 0 -> buf 0
    float4 ra0 = make_float4(0.f, 0.f, 0.f, 0.f), ra1 = ra0;
    if (aOk) {
        ra0 = *reinterpret_cast<const float4*>(aBase);
        ra1 = *reinterpret_cast<const float4*>(aBase + 4);
    }
    float4 rb = *reinterpret_cast<const float4*>(bBase);
    As[0][aK + 0][aRow] = ra0.x; As[0][aK + 1][aRow] = ra0.y;
    As[0][aK + 2][aRow] = ra0.z; As[0][aK + 3][aRow] = ra0.w;
    As[0][aK + 4][aRow] = ra1.x; As[0][aK + 5][aRow] = ra1.y;
    As[0][aK + 6][aRow] = ra1.z; As[0][aK + 7][aRow] = ra1.w;
    *reinterpret_cast<float4*>(&Bs[0][bK][bCol]) = rb;
    __syncthreads();

#pragma unroll
    for (int it = 0; it < 8; it++) {
        const int buf = it & 1;
        float4 na0 = make_float4(0.f, 0.f, 0.f, 0.f), na1 = na0, nb = na0;
        if (it + 1 < NIT) {
            int k0 = (it + 1) * BK;
            if (aOk) {
                na0 = *reinterpret_cast<const float4*>(aBase + k0);
                na1 = *reinterpret_cast<const float4*>(aBase + k0 + 4);
            }
            nb = *reinterpret_cast<const float4*>(bBase + (size_t)k0 * W1COLS);
        }
#pragma unroll
        for (int kk = 0; kk < BK; kk++) {
            ulonglong2 A01 = *reinterpret_cast<const ulonglong2*>(&As[buf][kk][ty * 8]);
            ulonglong2 A23 = *reinterpret_cast<const ulonglong2*>(&As[buf][kk][ty * 8 + 4]);
            float4 b4 = *reinterpret_cast<const float4*>(&Bs[buf][kk][tx * 4]);
            unsigned long long bb[4];
            BCAST_F32X2(bb[0], b4.x); BCAST_F32X2(bb[1], b4.y);
            BCAST_F32X2(bb[2], b4.z); BCAST_F32X2(bb[3], b4.w);
#pragma unroll
            for (int j = 0; j < 4; j++) {
                FMA_F32X2(acc2[0][j], A01.x, bb[j]);
                FMA_F32X2(acc2[1][j], A01.y, bb[j]);
                FMA_F32X2(acc2[2][j], A23.x, bb[j]);
                FMA_F32X2(acc2[3][j], A23.y, bb[j]);
            }
        }
        if (it + 1 < NIT) {
            const int nbuf = buf ^ 1;
            As[nbuf][aK + 0][aRow] = na0.x; As[nbuf][aK + 1][aRow] = na0.y;
            As[nbuf][aK + 2][aRow] = na0.z; As[nbuf][aK + 3][aRow] = na0.w;
            As[nbuf][aK + 4][aRow] = na1.x; As[nbuf][aK + 5][aRow] = na1.y;
            As[nbuf][aK + 6][aRow] = na1.z; As[nbuf][aK + 7][aRow] = na1.w;
            *reinterpret_cast<float4*>(&Bs[nbuf][bK][bCol]) = nb;
            __syncthreads();
        }
    }

#pragma unroll
    for (int ip = 0; ip < 4; ip++) {
        float2 c0 = *reinterpret_cast<float2*>(&acc2[ip][0]);
        float2 c1 = *reinterpret_cast<float2*>(&acc2[ip][1]);
        float2 c2 = *reinterpret_cast<float2*>(&acc2[ip][2]);
        float2 c3 = *reinterpret_cast<float2*>(&acc2[ip][3]);
        int row0 = rowBase + ty * 8 + ip * 2;
        int col = colBase + tx * 4;
        float4 lo = make_float4(c0.x, c1.x, c2.x, c3.x);
        float4 hi = make_float4(c0.y, c1.y, c2.y, c3.y);
        if (col < D) {
            if (row0 < NN)     *reinterpret_cast<float4*>(g_z + (size_t)row0 * D + col) = lo;
            if (row0 + 1 < NN) *reinterpret_cast<float4*>(g_z + (size_t)(row0 + 1) * D + col) = hi;
        } else {
            int oc = col - D;
            if (row0 < NN)     *reinterpret_cast<float4*>(out + (size_t)row0 * (H * D) + oc) = lo;
            if (row0 + 1 < NN) *reinterpret_cast<float4*>(out + (size_t)(row0 + 1) * (H * D) + oc) = hi;
        }
    }
}

// GEMM2: st[N,160] = z[N,64] @ Wst[64,192(pad)]
__global__ __launch_bounds__(256) void gemm2_kernel() {
    __shared__ __align__(16) float As[2][BK][BM + 4];
    __shared__ __align__(16) float Bs[2][BK][BN];
    const int tid = threadIdx.x;
    const int tx = tid & 15, ty = tid >> 4;
    const int rowBase = blockIdx.y * BM;
    const int colBase = blockIdx.x * BN;
    const int aRow = tid >> 1;
    const int aK   = (tid & 1) << 3;
    const int bK   = tid >> 4;
    const int bCol = (tid & 15) << 2;
    const int gr   = rowBase + aRow;
    const bool aOk = (gr < NN);
    const float* aBase = g_z + (size_t)(aOk ? gr : 0) * D + aK;
    const float* bBase = g_Wst + (size_t)bK * WSTLD + colBase + bCol;
    const int NIT = D / BK;   // 4

    unsigned long long acc2[4][4];
#pragma unroll
    for (int i = 0; i < 4; i++)
#pragma unroll
        for (int j = 0; j < 4; j++) acc2[i][j] = 0ull;

    float4 ra0 = make_float4(0.f, 0.f, 0.f, 0.f), ra1 = ra0;
    if (aOk) {
        ra0 = *reinterpret_cast<const float4*>(aBase);
        ra1 = *reinterpret_cast<const float4*>(aBase + 4);
    }
    float4 rb = *reinterpret_cast<const float4*>(bBase);
    As[0][aK + 0][aRow] = ra0.x; As[0][aK + 1][aRow] = ra0.y;
    As[0][aK + 2][aRow] = ra0.z; As[0][aK + 3][aRow] = ra0.w;
    As[0][aK + 4][aRow] = ra1.x; As[0][aK + 5][aRow] = ra1.y;
    As[0][aK + 6][aRow] = ra1.z; As[0][aK + 7][aRow] = ra1.w;
    *reinterpret_cast<float4*>(&Bs[0][bK][bCol]) = rb;
    __syncthreads();

#pragma unroll
    for (int it = 0; it < 4; it++) {
        const int buf = it & 1;
        float4 na0 = make_float4(0.f, 0.f, 0.f, 0.f), na1 = na0, nb = na0;
        if (it + 1 < NIT) {
            int k0 = (it + 1) * BK;
            if (aOk) {
                na0 = *reinterpret_cast<const float4*>(aBase + k0);
                na1 = *reinterpret_cast<const float4*>(aBase + k0 + 4);
            }
            nb = *reinterpret_cast<const float4*>(bBase + (size_t)k0 * WSTLD);
        }
#pragma unroll
        for (int kk = 0; kk < BK; kk++) {
            ulonglong2 A01 = *reinterpret_cast<const ulonglong2*>(&As[buf][kk][ty * 8]);
            ulonglong2 A23 = *reinterpret_cast<const ulonglong2*>(&As[buf][kk][ty * 8 + 4]);
            float4 b4 = *reinterpret_cast<const float4*>(&Bs[buf][kk][tx * 4]);
            unsigned long long bb[4];
            BCAST_F32X2(bb[0], b4.x); BCAST_F32X2(bb[1], b4.y);
            BCAST_F32X2(bb[2], b4.z); BCAST_F32X2(bb[3], b4.w);
#pragma unroll
            for (int j = 0; j < 4; j++) {
                FMA_F32X2(acc2[0][j], A01.x, bb[j]);
                FMA_F32X2(acc2[1][j], A01.y, bb[j]);
                FMA_F32X2(acc2[2][j], A23.x, bb[j]);
                FMA_F32X2(acc2[3][j], A23.y, bb[j]);
            }
        }
        if (it + 1 < NIT) {
            const int nbuf = buf ^ 1;
            As[nbuf][aK + 0][aRow] = na0.x; As[nbuf][aK + 1][aRow] = na0.y;
            As[nbuf][aK + 2][aRow] = na0.z; As[nbuf][aK + 3][aRow] = na0.w;
            As[nbuf][aK + 4][aRow] = na1.x; As[nbuf][aK + 5][aRow] = na1.y;
            As[nbuf][aK + 6][aRow] = na1.z; As[nbuf][aK + 7][aRow] = na1.w;
            *reinterpret_cast<float4*>(&Bs[nbuf][bK][bCol]) = nb;
            __syncthreads();
        }
    }

#pragma unroll
    for (int ip = 0; ip < 4; ip++) {
        float2 c0 = *reinterpret_cast<float2*>(&acc2[ip][0]);
        float2 c1 = *reinterpret_cast<float2*>(&acc2[ip][1]);
        float2 c2 = *reinterpret_cast<float2*>(&acc2[ip][2]);
        float2 c3 = *reinterpret_cast<float2*>(&acc2[ip][3]);
        int row0 = rowBase + ty * 8 + ip * 2;
        int col = colBase + tx * 4;
        if (col >= STCOLS) continue;
        float4 lo = make_float4(c0.x, c1.x, c2.x, c3.x);
        float4 hi = make_float4(c0.y, c1.y, c2.y, c3.y);
        if (row0 < NN)     *reinterpret_cast<float4*>(g_st + (size_t)row0 * STCOLS + col) = lo;
        if (row0 + 1 < NN) *reinterpret_cast<float4*>(g_st + (size_t)(row0 + 1) * STCOLS + col) = hi;
    }
}

// ---------------------------------------------------------------------------
// CSR build
// ---------------------------------------------------------------------------
__global__ void zero_deg_kernel() {
    int i = blockIdx.x * blockDim.x + threadIdx.x;
    if (i < NN) g_deg[i] = 0;
}

__global__ void hist_kernel(const int* __restrict__ dst) {
    int t = blockIdx.x * blockDim.x + threadIdx.x;
    if (t * 4 >= EE) return;
    int4 d4 = *reinterpret_cast<const int4*>(dst + t * 4);
    atomicAdd(&g_deg[d4.x], 1);
    atomicAdd(&g_deg[d4.y], 1);
    atomicAdd(&g_deg[d4.z], 1);
    atomicAdd(&g_deg[d4.w], 1);
}

#define SCAN_T 1024
#define SCAN_CHUNK 49
__global__ __launch_bounds__(SCAN_T) void scan_kernel() {
    __shared__ int sums[SCAN_T];
    int t = threadIdx.x;
    int beg = t * SCAN_CHUNK;
    int end = min(NN, beg + SCAN_CHUNK);
    int s = 0;
    for (int i = beg; i < end; i++) s += g_deg[i];
    sums[t] = s;
    __syncthreads();
#pragma unroll
    for (int off = 1; off < SCAN_T; off <<= 1) {
        int v = (t >= off) ? sums[t - off] : 0;
        __syncthreads();
        sums[t] += v;
        __syncthreads();
    }
    int run = (t == 0) ? 0 : sums[t - 1];
    for (int i = beg; i < end; i++) {
        g_rowptr[i] = run;
        g_cursor[i] = run;
        run += g_deg[i];
    }
    if (t == SCAN_T - 1) g_rowptr[NN] = sums[SCAN_T - 1];
}

__global__ void scatter_kernel(const int* __restrict__ src,
                               const int* __restrict__ dst,
                               const int* __restrict__ rel) {
    int e = blockIdx.x * blockDim.x + threadIdx.x;
    if (e >= EE) return;
    int d = dst[e];
    int pos = atomicAdd(&g_cursor[d], 1);
    g_csr[pos] = (unsigned)src[e] | ((unsigned)rel[e] << 16);
}

// ---------------------------------------------------------------------------
// Aggregate: one warp per destination node, 4-edge unrolled.
// Non-atomic += into d_out (self term already there from GEMM1).
// ---------------------------------------------------------------------------
__global__ __launch_bounds__(256) void aggregate_kernel(float* __restrict__ out) {
    int w = (blockIdx.x * blockDim.x + threadIdx.x) >> 5;
    if (w >= NN) return;
    int lane = threadIdx.x & 31;

    int beg = g_rowptr[w];
    int end = g_rowptr[w + 1];

    float acc[8];
#pragma unroll
    for (int i = 0; i < 8; i++) acc[i] = 0.f;

    const float* tvb = g_st + (size_t)w * STCOLS + 80;
    const int zoff = lane << 1;

    int i = beg;
    for (; i + 3 < end; i += 4) {
        unsigned p0 = __ldg(&g_csr[i]);
        unsigned p1 = __ldg(&g_csr[i + 1]);
        unsigned p2 = __ldg(&g_csr[i + 2]);
        unsigned p3 = __ldg(&g_csr[i + 3]);
        int s0 = p0 & 0xFFFFu, r0 = p0 >> 16;
        int s1 = p1 & 0xFFFFu, r1 = p1 >> 16;
        int s2 = p2 & 0xFFFFu, r2 = p2 >> 16;
        int s3 = p3 & 0xFFFFu, r3 = p3 >> 16;
        float4 sv0 = *reinterpret_cast<const float4*>(g_st + (size_t)s0 * STCOLS + (r0 << 2));
        float4 sv1 = *reinterpret_cast<const float4*>(g_st + (size_t)s1 * STCOLS + (r1 << 2));
        float4 sv2 = *reinterpret_cast<const float4*>(g_st + (size_t)s2 * STCOLS + (r2 << 2));
        float4 sv3 = *reinterpret_cast<const float4*>(g_st + (size_t)s3 * STCOLS + (r3 << 2));
        float4 tv0 = *reinterpret_cast<const float4*>(tvb + (r0 << 2));
        float4 tv1 = *reinterpret_cast<const float4*>(tvb + (r1 << 2));
        float4 tv2 = *reinterpret_cast<const float4*>(tvb + (r2 << 2));
        float4 tv3 = *reinterpret_cast<const float4*>(tvb + (r3 << 2));
        float2 z0 = *reinterpret_cast<const float2*>(g_z + (size_t)s0 * D + zoff);
        float2 z1 = *reinterpret_cast<const float2*>(g_z + (size_t)s1 * D + zoff);
        float2 z2 = *reinterpret_cast<const float2*>(g_z + (size_t)s2 * D + zoff);
        float2 z3 = *reinterpret_cast<const float2*>(g_z + (size_t)s3 * D + zoff);

#define EDGE_ACC(sv, tv, zv)                                            \
        {                                                               \
            float a0 = sv.x + tv.x, a1 = sv.y + tv.y;                   \
            float a2 = sv.z + tv.z, a3 = sv.w + tv.w;                   \
            a0 = fmaxf(a0, 0.01f * a0); a1 = fmaxf(a1, 0.01f * a1);     \
            a2 = fmaxf(a2, 0.01f * a2); a3 = fmaxf(a3, 0.01f * a3);     \
            acc[0] += a0 * zv.x; acc[1] += a0 * zv.y;                   \
            acc[2] += a1 * zv.x; acc[3] += a1 * zv.y;                   \
            acc[4] += a2 * zv.x; acc[5] += a2 * zv.y;                   \
            acc[6] += a3 * zv.x; acc[7] += a3 * zv.y;                   \
        }
        EDGE_ACC(sv0, tv0, z0)
        EDGE_ACC(sv1, tv1, z1)
        EDGE_ACC(sv2, tv2, z2)
        EDGE_ACC(sv3, tv3, z3)
    }
    for (; i < end; i++) {
        unsigned pc = __ldg(&g_csr[i]);
        int s = pc & 0xFFFFu, r = pc >> 16;
        float4 sv = *reinterpret_cast<const float4*>(g_st + (size_t)s * STCOLS + (r << 2));
        float4 tv = *reinterpret_cast<const float4*>(tvb + (r << 2));
        float2 zv = *reinterpret_cast<const float2*>(g_z + (size_t)s * D + zoff);
        EDGE_ACC(sv, tv, zv)
    }
#undef EDGE_ACC

    float* o = out + (size_t)w * (H * D) + zoff;
#pragma unroll
    for (int hh = 0; hh < H; hh++) {
        float2* op = reinterpret_cast<float2*>(o + hh * D);
        float2 cur = *op;
        cur.x += acc[hh * 2 + 0];
        cur.y += acc[hh * 2 + 1];
        *op = cur;
    }
}

// ---------------------------------------------------------------------------
extern "C" void kernel_launch(void* const* d_in, const int* in_sizes, int n_in,
                              void* d_out, int out_size) {
    const float* h_in      = (const float*)d_in[0];
    const float* fc_w      = (const float*)d_in[1];
    const float* self_fc_w = (const float*)d_in[2];
    const float* attn_w    = (const float*)d_in[3];
    const float* w_comp    = (const float*)d_in[4];
    const int*   src       = (const int*)d_in[5];
    const int*   dst       = (const int*)d_in[6];
    const int*   rel       = (const int*)d_in[7];
    float* out = (float*)d_out;

    // weight prep
    build_wst_kernel<<<(D * WSTLD + 255) / 256, 256>>>(w_comp, attn_w);
    build_w1_kernel<<<(INDIM * W1COLS + 255) / 256, 256>>>(fc_w, self_fc_w);

    // CSR build
    zero_deg_kernel<<<(NN + 255) / 256, 256>>>();
    hist_kernel<<<(EE / 4 + 255) / 256, 256>>>(dst);
    scan_kernel<<<1, SCAN_T>>>();
    scatter_kernel<<<(EE + 255) / 256, 256>>>(src, dst, rel);

    // node projections
    dim3 g1(W1COLS / BN, (NN + BM - 1) / BM);   // 5 x 391
    gemm1_kernel<<<g1, 256>>>(h_in, out);
    dim3 g2(WSTLD / BN, (NN + BM - 1) / BM);    // 3 x 391
    gemm2_kernel<<<g2, 256>>>();

    // edge aggregation
    aggregate_kernel<<<(NN * 32 + 255) / 256, 256>>>(out);
}

// round 14
// speedup vs baseline: 1.1138x; 1.1138x over previous
#include <cuda_runtime.h>
#include <cuda_bf16.h>
#include <cstdint>

#define NN      50000
#define EE      800000
#define INDIM   128
#define D       64
#define H       4
#define NR      20
#define NB      8
#define STCOLS  160
#define W1COLS  320
#define WSTLD   192

// ---- static scratch ----
__device__ __align__(16) float g_z[NN * D];
__device__ __align__(16) float g_st[NN * STCOLS];
__device__ __align__(16) float g_Wst[D * WSTLD];
__device__ __align__(16) __nv_bfloat16 g_W1hi[W1COLS * INDIM];
__device__ __align__(16) __nv_bfloat16 g_W1lo[W1COLS * INDIM];
__device__ int g_deg[NN];
__device__ int g_rowptr[NN + 1];
__device__ int g_cursor[NN];
__device__ unsigned g_csr[EE];

// packed fp32x2 FMA (gemm2)
#define FMA_F32X2(d, a, b) asm("fma.rn.f32x2 %0, %1, %2, %0;" : "+l"(d) : "l"(a), "l"(b))
#define BCAST_F32X2(d, s)  asm("mov.b64 %0, {%1, %1};" : "=l"(d) : "f"(s))

__device__ __forceinline__ uint32_t smem_u32(const void* p) {
    uint32_t a;
    asm("{ .reg .u64 t; cvta.to.shared.u64 t, %1; cvt.u32.u64 %0, t; }" : "=r"(a) : "l"(p));
    return a;
}
__device__ __forceinline__ void ldsm_x4(uint32_t* r, uint32_t addr) {
    asm volatile("ldmatrix.sync.aligned.m8n8.x4.shared.b16 {%0,%1,%2,%3}, [%4];"
                 : "=r"(r[0]), "=r"(r[1]), "=r"(r[2]), "=r"(r[3]) : "r"(addr));
}
#define MMA_BF16(c, a, b0, b1)                                                   \
    asm volatile("mma.sync.aligned.m16n8k16.row.col.f32.bf16.bf16.f32 "          \
                 "{%0,%1,%2,%3}, {%4,%5,%6,%7}, {%8,%9}, {%0,%1,%2,%3};"         \
                 : "+f"((c)[0]), "+f"((c)[1]), "+f"((c)[2]), "+f"((c)[3])        \
                 : "r"((a)[0]), "r"((a)[1]), "r"((a)[2]), "r"((a)[3]),           \
                   "r"(b0), "r"(b1))

// ---------------------------------------------------------------------------
__global__ void build_wst_kernel(const float* __restrict__ w_comp,
                                 const float* __restrict__ aw) {
    int idx = blockIdx.x * blockDim.x + threadIdx.x;
    if (idx >= D * WSTLD) return;
    int c  = idx / WSTLD;
    int jj = idx % WSTLD;
    if (jj >= STCOLS) { g_Wst[idx] = 0.f; return; }
    int r, hh, cc;
    if (jj < 80) { r = jj >> 2; hh = jj & 3; cc = c; }
    else         { int j2 = jj - 80; r = j2 >> 2; hh = j2 & 3; cc = c + D; }
    float acc = 0.f;
#pragma unroll
    for (int b = 0; b < NB; b++)
        acc += w_comp[r * NB + b] * aw[b * (2 * D * H) + cc * H + hh];
    g_Wst[idx] = acc;
}

// split W1 (fc^T rows then self^T rows) into bf16 hi/lo, [320][128] row-major
__global__ void build_w1bf16_kernel(const float* __restrict__ fc_w,
                                    const float* __restrict__ self_fc_w) {
    int idx = blockIdx.x * blockDim.x + threadIdx.x;
    if (idx >= W1COLS * INDIM) return;
    int j = idx >> 7, k = idx & 127;
    float w = (j < D) ? fc_w[j * INDIM + k] : self_fc_w[(j - D) * INDIM + k];
    __nv_bfloat16 hi = __float2bfloat16_rn(w);
    g_W1hi[idx] = hi;
    g_W1lo[idx] = __float2bfloat16_rn(w - __bfloat162float(hi));
}

// ---------------------------------------------------------------------------
// Tensor-core GEMM1 via mma.sync bf16 3-split.
// CTA: 128 rows x 320 cols (5 tiles of 64). 8 warps, 32x32 warp tiles.
// A smem: [128][136] bf16 hi+lo (row-major, k padded 128->136).
// B smem: [64][136] bf16 hi+lo (n-major rows; .col operand via ldmatrix).
// ---------------------------------------------------------------------------
#define AST      272          // smem row stride bytes (136 bf16)
#define SM_A_HI  0
#define SM_A_LO  34816        // 128*272
#define SM_B_HI  69632
#define SM_B_LO  87040        // + 64*272
#define SM_TOT   104448

__device__ __forceinline__ uint32_t pack_bf16x2(float a, float b) {
    unsigned short ua = __bfloat16_as_ushort(__float2bfloat16_rn(a));
    unsigned short ub = __bfloat16_as_ushort(__float2bfloat16_rn(b));
    return (uint32_t)ua | ((uint32_t)ub << 16);
}

__global__ __launch_bounds__(256, 1) void tc_gemm1_kernel(
    const float* __restrict__ A, float* __restrict__ out) {
    extern __shared__ __align__(16) char smem[];
    const uint32_t sb = smem_u32(smem);
    const int tid = threadIdx.x;
    const int lane = tid & 31;
    const int wid = tid >> 5;

    // ---- A conversion: row = tid/2, 64 k values ----
    {
        int row = tid >> 1;
        int kh  = (tid & 1) << 6;
        int gr  = blockIdx.x * 128 + row;
        bool ok = gr < NN;
        const float* ap = A + (size_t)(ok ? gr : 0) * INDIM + kh;
#pragma unroll
        for (int g8 = 0; g8 < 8; g8++) {
            int k = kh + g8 * 8;
            float v[8];
            if (ok) {
                float4 v0 = *reinterpret_cast<const float4*>(ap + g8 * 8);
                float4 v1 = *reinterpret_cast<const float4*>(ap + g8 * 8 + 4);
                v[0]=v0.x; v[1]=v0.y; v[2]=v0.z; v[3]=v0.w;
                v[4]=v1.x; v[5]=v1.y; v[6]=v1.z; v[7]=v1.w;
            } else {
#pragma unroll
                for (int i = 0; i < 8; i++) v[i] = 0.f;
            }
            uint32_t hi[4], lo[4];
#pragma unroll
            for (int p = 0; p < 4; p++) {
                float h0 = __bfloat162float(__float2bfloat16_rn(v[p*2]));
                float h1 = __bfloat162float(__float2bfloat16_rn(v[p*2+1]));
                hi[p] = pack_bf16x2(v[p*2], v[p*2+1]);
                lo[p] = pack_bf16x2(v[p*2] - h0, v[p*2+1] - h1);
            }
            uint32_t off = (uint32_t)row * AST + k * 2;
            *reinterpret_cast<uint4*>(smem + SM_A_HI + off) = make_uint4(hi[0],hi[1],hi[2],hi[3]);
            *reinterpret_cast<uint4*>(smem + SM_A_LO + off) = make_uint4(lo[0],lo[1],lo[2],lo[3]);
        }
    }
    __syncthreads();

    const int warpM = wid & 3;       // 4 m-tiles of 32
    const int warpN = wid >> 2;      // 2 n-tiles of 32
    const int arow = (lane & 7) + ((lane >> 3) & 1) * 8;
    const int akb  = (lane >> 4) * 8;
    const int brow = (lane & 7) + ((lane >> 4) & 1) * 8;
    const int bkb  = ((lane >> 3) & 1) * 8;
    const uint32_t aAddr = sb + SM_A_HI + (uint32_t)(warpM * 32 + arow) * AST + akb * 2;
    const uint32_t bAddr = sb + SM_B_HI + (uint32_t)(warpN * 32 + brow) * AST + bkb * 2;

    for (int nt = 0; nt < 5; nt++) {
        // ---- B tile load: n = tid/4, 32 k values ----
        {
            int n  = tid >> 2;
            int kq = (tid & 3) << 5;
            const __nv_bfloat16* sh = g_W1hi + (size_t)(nt * 64 + n) * INDIM + kq;
            const __nv_bfloat16* sl = g_W1lo + (size_t)(nt * 64 + n) * INDIM + kq;
            uint32_t doff = (uint32_t)n * AST + kq * 2;
#pragma unroll
            for (int i = 0; i < 4; i++) {
                *reinterpret_cast<uint4*>(smem + SM_B_HI + doff + i * 16) =
                    *reinterpret_cast<const uint4*>(sh + i * 8);
                *reinterpret_cast<uint4*>(smem + SM_B_LO + doff + i * 16) =
                    *reinterpret_cast<const uint4*>(sl + i * 8);
            }
        }
        __syncthreads();

        float c[2][4][4];
#pragma unroll
        for (int mf = 0; mf < 2; mf++)
#pragma unroll
            for (int nf = 0; nf < 4; nf++)
#pragma unroll
                for (int q = 0; q < 4; q++) c[mf][nf][q] = 0.f;

#pragma unroll
        for (int kt = 0; kt < 8; kt++) {
            uint32_t ah[2][4], al[2][4], bh[2][4], bl[2][4];
            ldsm_x4(ah[0], aAddr + kt * 32);
            ldsm_x4(ah[1], aAddr + 16 * AST + kt * 32);
            ldsm_x4(al[0], aAddr + SM_A_LO + kt * 32);
            ldsm_x4(al[1], aAddr + SM_A_LO + 16 * AST + kt * 32);
            ldsm_x4(bh[0], bAddr + kt * 32);
            ldsm_x4(bh[1], bAddr + 16 * AST + kt * 32);
            ldsm_x4(bl[0], bAddr + (SM_B_LO - SM_B_HI) + kt * 32);
            ldsm_x4(bl[1], bAddr + (SM_B_LO - SM_B_HI) + 16 * AST + kt * 32);
#pragma unroll
            for (int mf = 0; mf < 2; mf++)
#pragma unroll
                for (int nf = 0; nf < 4; nf++) {
                    int nh = nf >> 1, o = (nf & 1) * 2;
                    MMA_BF16(c[mf][nf], ah[mf], bh[nh][o], bh[nh][o + 1]);
                    MMA_BF16(c[mf][nf], ah[mf], bl[nh][o], bl[nh][o + 1]);
                    MMA_BF16(c[mf][nf], al[mf], bh[nh][o], bh[nh][o + 1]);
                }
        }

        // ---- epilogue: direct routed float2 stores ----
#pragma unroll
        for (int mf = 0; mf < 2; mf++) {
            int r0 = blockIdx.x * 128 + warpM * 32 + mf * 16 + (lane >> 2);
#pragma unroll
            for (int nf = 0; nf < 4; nf++) {
                int colL = warpN * 32 + nf * 8 + (lane & 3) * 2;
                int j = nt * 64 + colL;
                float2 v01 = make_float2(c[mf][nf][0], c[mf][nf][1]);
                float2 v23 = make_float2(c[mf][nf][2], c[mf][nf][3]);
                if (j < D) {
                    if (r0 < NN)     *reinterpret_cast<float2*>(g_z + (size_t)r0 * D + j) = v01;
                    if (r0 + 8 < NN) *reinterpret_cast<float2*>(g_z + (size_t)(r0 + 8) * D + j) = v23;
                } else {
                    int oc = j - D;
                    if (r0 < NN)     *reinterpret_cast<float2*>(out + (size_t)r0 * (H * D) + oc) = v01;
                    if (r0 + 8 < NN) *reinterpret_cast<float2*>(out + (size_t)(r0 + 8) * (H * D) + oc) = v23;
                }
            }
        }
        __syncthreads();
    }
}

// ---------------------------------------------------------------------------
// GEMM2 (f32x2): st[N,160] = z[N,64] @ Wst[64,192(pad)]
// ---------------------------------------------------------------------------
#define BM 128
#define BN 64
#define BK 16

__global__ __launch_bounds__(256) void gemm2_kernel() {
    __shared__ __align__(16) float As[2][BK][BM + 4];
    __shared__ __align__(16) float Bs[2][BK][BN];
    const int tid = threadIdx.x;
    const int tx = tid & 15, ty = tid >> 4;
    const int rowBase = blockIdx.y * BM;
    const int colBase = blockIdx.x * BN;
    const int aRow = tid >> 1;
    const int aK   = (tid & 1) << 3;
    const int bK   = tid >> 4;
    const int bCol = (tid & 15) << 2;
    const int gr   = rowBase + aRow;
    const bool aOk = (gr < NN);
    const float* aBase = g_z + (size_t)(aOk ? gr : 0) * D + aK;
    const float* bBase = g_Wst + (size_t)bK * WSTLD + colBase + bCol;
    const int NIT = D / BK;

    unsigned long long acc2[4][4];
#pragma unroll
    for (int i = 0; i < 4; i++)
#pragma unroll
        for (int j = 0; j < 4; j++) acc2[i][j] = 0ull;

    float4 ra0 = make_float4(0.f, 0.f, 0.f, 0.f), ra1 = ra0;
    if (aOk) {
        ra0 = *reinterpret_cast<const float4*>(aBase);
        ra1 = *reinterpret_cast<const float4*>(aBase + 4);
    }
    float4 rb = *reinterpret_cast<const float4*>(bBase);
    As[0][aK + 0][aRow] = ra0.x; As[0][aK + 1][aRow] = ra0.y;
    As[0][aK + 2][aRow] = ra0.z; As[0][aK + 3][aRow] = ra0.w;
    As[0][aK + 4][aRow] = ra1.x; As[0][aK + 5][aRow] = ra1.y;
    As[0][aK + 6][aRow] = ra1.z; As[0][aK + 7][aRow] = ra1.w;
    *reinterpret_cast<float4*>(&Bs[0][bK][bCol]) = rb;
    __syncthreads();

#pragma unroll
    for (int it = 0; it < 4; it++) {
        const int buf = it & 1;
        float4 na0 = make_float4(0.f, 0.f, 0.f, 0.f), na1 = na0, nb = na0;
        if (it + 1 < NIT) {
            int k0 = (it + 1) * BK;
            if (aOk) {
                na0 = *reinterpret_cast<const float4*>(aBase + k0);
                na1 = *reinterpret_cast<const float4*>(aBase + k0 + 4);
            }
            nb = *reinterpret_cast<const float4*>(bBase + (size_t)k0 * WSTLD);
        }
#pragma unroll
        for (int kk = 0; kk < BK; kk++) {
            ulonglong2 A01 = *reinterpret_cast<const ulonglong2*>(&As[buf][kk][ty * 8]);
            ulonglong2 A23 = *reinterpret_cast<const ulonglong2*>(&As[buf][kk][ty * 8 + 4]);
            float4 b4 = *reinterpret_cast<const float4*>(&Bs[buf][kk][tx * 4]);
            unsigned long long bb[4];
            BCAST_F32X2(bb[0], b4.x); BCAST_F32X2(bb[1], b4.y);
            BCAST_F32X2(bb[2], b4.z); BCAST_F32X2(bb[3], b4.w);
#pragma unroll
            for (int j = 0; j < 4; j++) {
                FMA_F32X2(acc2[0][j], A01.x, bb[j]);
                FMA_F32X2(acc2[1][j], A01.y, bb[j]);
                FMA_F32X2(acc2[2][j], A23.x, bb[j]);
                FMA_F32X2(acc2[3][j], A23.y, bb[j]);
            }
        }
        if (it + 1 < NIT) {
            const int nbuf = buf ^ 1;
            As[nbuf][aK + 0][aRow] = na0.x; As[nbuf][aK + 1][aRow] = na0.y;
            As[nbuf][aK + 2][aRow] = na0.z; As[nbuf][aK + 3][aRow] = na0.w;
            As[nbuf][aK + 4][aRow] = na1.x; As[nbuf][aK + 5][aRow] = na1.y;
            As[nbuf][aK + 6][aRow] = na1.z; As[nbuf][aK + 7][aRow] = na1.w;
            *reinterpret_cast<float4*>(&Bs[nbuf][bK][bCol]) = nb;
            __syncthreads();
        }
    }

#pragma unroll
    for (int ip = 0; ip < 4; ip++) {
        float2 c0 = *reinterpret_cast<float2*>(&acc2[ip][0]);
        float2 c1 = *reinterpret_cast<float2*>(&acc2[ip][1]);
        float2 c2 = *reinterpret_cast<float2*>(&acc2[ip][2]);
        float2 c3 = *reinterpret_cast<float2*>(&acc2[ip][3]);
        int row0 = rowBase + ty * 8 + ip * 2;
        int col = colBase + tx * 4;
        if (col >= STCOLS) continue;
        float4 lo = make_float4(c0.x, c1.x, c2.x, c3.x);
        float4 hi = make_float4(c0.y, c1.y, c2.y, c3.y);
        if (row0 < NN)     *reinterpret_cast<float4*>(g_st + (size_t)row0 * STCOLS + col) = lo;
        if (row0 + 1 < NN) *reinterpret_cast<float4*>(g_st + (size_t)(row0 + 1) * STCOLS + col) = hi;
    }
}

// ---------------------------------------------------------------------------
// CSR build
// ---------------------------------------------------------------------------
__global__ void zero_deg_kernel() {
    int i = blockIdx.x * blockDim.x + threadIdx.x;
    if (i < NN) g_deg[i] = 0;
}

__global__ void hist_kernel(const int* __restrict__ dst) {
    int t = blockIdx.x * blockDim.x + threadIdx.x;
    if (t * 4 >= EE) return;
    int4 d4 = *reinterpret_cast<const int4*>(dst + t * 4);
    atomicAdd(&g_deg[d4.x], 1);
    atomicAdd(&g_deg[d4.y], 1);
    atomicAdd(&g_deg[d4.z], 1);
    atomicAdd(&g_deg[d4.w], 1);
}

#define SCAN_T 1024
#define SCAN_CHUNK 49
__global__ __launch_bounds__(SCAN_T) void scan_kernel() {
    __shared__ int sums[SCAN_T];
    int t = threadIdx.x;
    int beg = t * SCAN_CHUNK;
    int end = min(NN, beg + SCAN_CHUNK);
    int s = 0;
    for (int i = beg; i < end; i++) s += g_deg[i];
    sums[t] = s;
    __syncthreads();
#pragma unroll
    for (int off = 1; off < SCAN_T; off <<= 1) {
        int v = (t >= off) ? sums[t - off] : 0;
        __syncthreads();
        sums[t] += v;
        __syncthreads();
    }
    int run = (t == 0) ? 0 : sums[t - 1];
    for (int i = beg; i < end; i++) {
        g_rowptr[i] = run;
        g_cursor[i] = run;
        run += g_deg[i];
    }
    if (t == SCAN_T - 1) g_rowptr[NN] = sums[SCAN_T - 1];
}

__global__ void scatter_kernel(const int* __restrict__ src,
                               const int* __restrict__ dst,
                               const int* __restrict__ rel) {
    int e = blockIdx.x * blockDim.x + threadIdx.x;
    if (e >= EE) return;
    int d = dst[e];
    int pos = atomicAdd(&g_cursor[d], 1);
    g_csr[pos] = (unsigned)src[e] | ((unsigned)rel[e] << 16);
}

// ---------------------------------------------------------------------------
// Aggregate: one warp per destination node, 4-edge unrolled.
// ---------------------------------------------------------------------------
__global__ __launch_bounds__(256) void aggregate_kernel(float* __restrict__ out) {
    int w = (blockIdx.x * blockDim.x + threadIdx.x) >> 5;
    if (w >= NN) return;
    int lane = threadIdx.x & 31;

    int beg = g_rowptr[w];
    int end = g_rowptr[w + 1];

    float acc[8];
#pragma unroll
    for (int i = 0; i < 8; i++) acc[i] = 0.f;

    const float* tvb = g_st + (size_t)w * STCOLS + 80;
    const int zoff = lane << 1;

    int i = beg;
    for (; i + 3 < end; i += 4) {
        unsigned p0 = __ldg(&g_csr[i]);
        unsigned p1 = __ldg(&g_csr[i + 1]);
        unsigned p2 = __ldg(&g_csr[i + 2]);
        unsigned p3 = __ldg(&g_csr[i + 3]);
        int s0 = p0 & 0xFFFFu, r0 = p0 >> 16;
        int s1 = p1 & 0xFFFFu, r1 = p1 >> 16;
        int s2 = p2 & 0xFFFFu, r2 = p2 >> 16;
        int s3 = p3 & 0xFFFFu, r3 = p3 >> 16;
        float4 sv0 = *reinterpret_cast<const float4*>(g_st + (size_t)s0 * STCOLS + (r0 << 2));
        float4 sv1 = *reinterpret_cast<const float4*>(g_st + (size_t)s1 * STCOLS + (r1 << 2));
        float4 sv2 = *reinterpret_cast<const float4*>(g_st + (size_t)s2 * STCOLS + (r2 << 2));
        float4 sv3 = *reinterpret_cast<const float4*>(g_st + (size_t)s3 * STCOLS + (r3 << 2));
        float4 tv0 = *reinterpret_cast<const float4*>(tvb + (r0 << 2));
        float4 tv1 = *reinterpret_cast<const float4*>(tvb + (r1 << 2));
        float4 tv2 = *reinterpret_cast<const float4*>(tvb + (r2 << 2));
        float4 tv3 = *reinterpret_cast<const float4*>(tvb + (r3 << 2));
        float2 z0 = *reinterpret_cast<const float2*>(g_z + (size_t)s0 * D + zoff);
        float2 z1 = *reinterpret_cast<const float2*>(g_z + (size_t)s1 * D + zoff);
        float2 z2 = *reinterpret_cast<const float2*>(g_z + (size_t)s2 * D + zoff);
        float2 z3 = *reinterpret_cast<const float2*>(g_z + (size_t)s3 * D + zoff);

#define EDGE_ACC(sv, tv, zv)                                            \
        {                                                               \
            float a0 = sv.x + tv.x, a1 = sv.y + tv.y;                   \
            float a2 = sv.z + tv.z, a3 = sv.w + tv.w;                   \
            a0 = fmaxf(a0, 0.01f * a0); a1 = fmaxf(a1, 0.01f * a1);     \
            a2 = fmaxf(a2, 0.01f * a2); a3 = fmaxf(a3, 0.01f * a3);     \
            acc[0] += a0 * zv.x; acc[1] += a0 * zv.y;                   \
            acc[2] += a1 * zv.x; acc[3] += a1 * zv.y;                   \
            acc[4] += a2 * zv.x; acc[5] += a2 * zv.y;                   \
            acc[6] += a3 * zv.x; acc[7] += a3 * zv.y;                   \
        }
        EDGE_ACC(sv0, tv0, z0)
        EDGE_ACC(sv1, tv1, z1)
        EDGE_ACC(sv2, tv2, z2)
        EDGE_ACC(sv3, tv3, z3)
    }
    for (; i < end; i++) {
        unsigned pc = __ldg(&g_csr[i]);
        int s = pc & 0xFFFFu, r = pc >> 16;
        float4 sv = *reinterpret_cast<const float4*>(g_st + (size_t)s * STCOLS + (r << 2));
        float4 tv = *reinterpret_cast<const float4*>(tvb + (r << 2));
        float2 zv = *reinterpret_cast<const float2*>(g_z + (size_t)s * D + zoff);
        EDGE_ACC(sv, tv, zv)
    }
#undef EDGE_ACC

    float* o = out + (size_t)w * (H * D) + zoff;
#pragma unroll
    for (int hh = 0; hh < H; hh++) {
        float2* op = reinterpret_cast<float2*>(o + hh * D);
        float2 cur = *op;
        cur.x += acc[hh * 2 + 0];
        cur.y += acc[hh * 2 + 1];
        *op = cur;
    }
}

// ---------------------------------------------------------------------------
extern "C" void kernel_launch(void* const* d_in, const int* in_sizes, int n_in,
                              void* d_out, int out_size) {
    const float* h_in      = (const float*)d_in[0];
    const float* fc_w      = (const float*)d_in[1];
    const float* self_fc_w = (const float*)d_in[2];
    const float* attn_w    = (const float*)d_in[3];
    const float* w_comp    = (const float*)d_in[4];
    const int*   src       = (const int*)d_in[5];
    const int*   dst       = (const int*)d_in[6];
    const int*   rel       = (const int*)d_in[7];
    float* out = (float*)d_out;

    cudaFuncSetAttribute(tc_gemm1_kernel,
                         cudaFuncAttributeMaxDynamicSharedMemorySize, SM_TOT);

    build_wst_kernel<<<(D * WSTLD + 255) / 256, 256>>>(w_comp, attn_w);
    build_w1bf16_kernel<<<(W1COLS * INDIM + 255) / 256, 256>>>(fc_w, self_fc_w);

    zero_deg_kernel<<<(NN + 255) / 256, 256>>>();
    hist_kernel<<<(EE / 4 + 255) / 256, 256>>>(dst);
    scan_kernel<<<1, SCAN_T>>>();
    scatter_kernel<<<(EE + 255) / 256, 256>>>(src, dst, rel);

    tc_gemm1_kernel<<<(NN + 127) / 128, 256, SM_TOT>>>(h_in, out);

    dim3 g2(WSTLD / BN, (NN + BM - 1) / BM);
    gemm2_kernel<<<g2, 256>>>();

    aggregate_kernel<<<(NN * 32 + 255) / 256, 256>>>(out);
}

// round 15
// speedup vs baseline: 1.1216x; 1.0070x over previous
#include <cuda_runtime.h>
#include <cuda_bf16.h>
#include <cstdint>

#define NN      50000
#define EE      800000
#define INDIM   128
#define D       64
#define H       4
#define NR      20
#define NB      8
#define STCOLS  160
#define W1COLS  320
#define WSTLD   192

// ---- static scratch ----
__device__ __align__(16) float g_z[NN * D];
__device__ __align__(16) float g_st[NN * STCOLS];
__device__ __align__(16) float g_Wst[D * WSTLD];
__device__ __align__(16) __nv_bfloat16 g_W1hi[W1COLS * INDIM];
__device__ __align__(16) __nv_bfloat16 g_W1lo[W1COLS * INDIM];
__device__ int g_deg[NN];
__device__ int g_rowptr[NN + 1];
__device__ int g_cursor[NN];
__device__ unsigned g_csr[EE];

// packed fp32x2 FMA (gemm2)
#define FMA_F32X2(d, a, b) asm("fma.rn.f32x2 %0, %1, %2, %0;" : "+l"(d) : "l"(a), "l"(b))
#define BCAST_F32X2(d, s)  asm("mov.b64 %0, {%1, %1};" : "=l"(d) : "f"(s))

__device__ __forceinline__ uint32_t smem_u32(const void* p) {
    uint32_t a;
    asm("{ .reg .u64 t; cvta.to.shared.u64 t, %1; cvt.u32.u64 %0, t; }" : "=r"(a) : "l"(p));
    return a;
}
__device__ __forceinline__ void ldsm_x4(uint32_t* r, uint32_t addr) {
    asm volatile("ldmatrix.sync.aligned.m8n8.x4.shared.b16 {%0,%1,%2,%3}, [%4];"
                 : "=r"(r[0]), "=r"(r[1]), "=r"(r[2]), "=r"(r[3]) : "r"(addr));
}
#define MMA_BF16(c, a, b0, b1)                                                   \
    asm volatile("mma.sync.aligned.m16n8k16.row.col.f32.bf16.bf16.f32 "          \
                 "{%0,%1,%2,%3}, {%4,%5,%6,%7}, {%8,%9}, {%0,%1,%2,%3};"         \
                 : "+f"((c)[0]), "+f"((c)[1]), "+f"((c)[2]), "+f"((c)[3])        \
                 : "r"((a)[0]), "r"((a)[1]), "r"((a)[2]), "r"((a)[3]),           \
                   "r"(b0), "r"(b1))

// ---------------------------------------------------------------------------
__global__ void build_wst_kernel(const float* __restrict__ w_comp,
                                 const float* __restrict__ aw) {
    int idx = blockIdx.x * blockDim.x + threadIdx.x;
    if (idx >= D * WSTLD) return;
    int c  = idx / WSTLD;
    int jj = idx % WSTLD;
    if (jj >= STCOLS) { g_Wst[idx] = 0.f; return; }
    int r, hh, cc;
    if (jj < 80) { r = jj >> 2; hh = jj & 3; cc = c; }
    else         { int j2 = jj - 80; r = j2 >> 2; hh = j2 & 3; cc = c + D; }
    float acc = 0.f;
#pragma unroll
    for (int b = 0; b < NB; b++)
        acc += w_comp[r * NB + b] * aw[b * (2 * D * H) + cc * H + hh];
    g_Wst[idx] = acc;
}

// split W1 (fc^T rows then self^T rows) into bf16 hi/lo, [320][128] row-major
__global__ void build_w1bf16_kernel(const float* __restrict__ fc_w,
                                    const float* __restrict__ self_fc_w) {
    int idx = blockIdx.x * blockDim.x + threadIdx.x;
    if (idx >= W1COLS * INDIM) return;
    int j = idx >> 7, k = idx & 127;
    float w = (j < D) ? fc_w[j * INDIM + k] : self_fc_w[(j - D) * INDIM + k];
    __nv_bfloat16 hi = __float2bfloat16_rn(w);
    g_W1hi[idx] = hi;
    g_W1lo[idx] = __float2bfloat16_rn(w - __bfloat162float(hi));
}

// ---------------------------------------------------------------------------
// Tensor-core GEMM1 via mma.sync bf16 3-split.
// CTA: 128 rows x 320 cols (5 tiles of 64). 8 warps, 32x32 warp tiles.
// A smem: [128][136] bf16 hi+lo (row-major, k padded 128->136).
// B smem: [64][136] bf16 hi+lo (n-major rows; .col operand via ldmatrix).
// ---------------------------------------------------------------------------
#define AST      272          // smem row stride bytes (136 bf16)
#define SM_A_HI  0
#define SM_A_LO  34816        // 128*272
#define SM_B_HI  69632
#define SM_B_LO  87040        // + 64*272
#define SM_TOT   104448

__device__ __forceinline__ uint32_t pack_bf16x2(float a, float b) {
    unsigned short ua = __bfloat16_as_ushort(__float2bfloat16_rn(a));
    unsigned short ub = __bfloat16_as_ushort(__float2bfloat16_rn(b));
    return (uint32_t)ua | ((uint32_t)ub << 16);
}

__global__ __launch_bounds__(256, 1) void tc_gemm1_kernel(
    const float* __restrict__ A, float* __restrict__ out) {
    extern __shared__ __align__(16) char smem[];
    const uint32_t sb = smem_u32(smem);
    const int tid = threadIdx.x;
    const int lane = tid & 31;
    const int wid = tid >> 5;

    // ---- A conversion: row = tid/2, 64 k values ----
    {
        int row = tid >> 1;
        int kh  = (tid & 1) << 6;
        int gr  = blockIdx.x * 128 + row;
        bool ok = gr < NN;
        const float* ap = A + (size_t)(ok ? gr : 0) * INDIM + kh;
#pragma unroll
        for (int g8 = 0; g8 < 8; g8++) {
            int k = kh + g8 * 8;
            float v[8];
            if (ok) {
                float4 v0 = *reinterpret_cast<const float4*>(ap + g8 * 8);
                float4 v1 = *reinterpret_cast<const float4*>(ap + g8 * 8 + 4);
                v[0]=v0.x; v[1]=v0.y; v[2]=v0.z; v[3]=v0.w;
                v[4]=v1.x; v[5]=v1.y; v[6]=v1.z; v[7]=v1.w;
            } else {
#pragma unroll
                for (int i = 0; i < 8; i++) v[i] = 0.f;
            }
            uint32_t hi[4], lo[4];
#pragma unroll
            for (int p = 0; p < 4; p++) {
                float h0 = __bfloat162float(__float2bfloat16_rn(v[p*2]));
                float h1 = __bfloat162float(__float2bfloat16_rn(v[p*2+1]));
                hi[p] = pack_bf16x2(v[p*2], v[p*2+1]);
                lo[p] = pack_bf16x2(v[p*2] - h0, v[p*2+1] - h1);
            }
            uint32_t off = (uint32_t)row * AST + k * 2;
            *reinterpret_cast<uint4*>(smem + SM_A_HI + off) = make_uint4(hi[0],hi[1],hi[2],hi[3]);
            *reinterpret_cast<uint4*>(smem + SM_A_LO + off) = make_uint4(lo[0],lo[1],lo[2],lo[3]);
        }
    }
    __syncthreads();

    const int warpM = wid & 3;       // 4 m-tiles of 32
    const int warpN = wid >> 2;      // 2 n-tiles of 32
    const int arow = (lane & 7) + ((lane >> 3) & 1) * 8;
    const int akb  = (lane >> 4) * 8;
    const int brow = (lane & 7) + ((lane >> 4) & 1) * 8;
    const int bkb  = ((lane >> 3) & 1) * 8;
    const uint32_t aAddr = sb + SM_A_HI + (uint32_t)(warpM * 32 + arow) * AST + akb * 2;
    const uint32_t bAddr = sb + SM_B_HI + (uint32_t)(warpN * 32 + brow) * AST + bkb * 2;

    for (int nt = 0; nt < 5; nt++) {
        // ---- B tile load: n = tid/4, 32 k values ----
        {
            int n  = tid >> 2;
            int kq = (tid & 3) << 5;
            const __nv_bfloat16* sh = g_W1hi + (size_t)(nt * 64 + n) * INDIM + kq;
            const __nv_bfloat16* sl = g_W1lo + (size_t)(nt * 64 + n) * INDIM + kq;
            uint32_t doff = (uint32_t)n * AST + kq * 2;
#pragma unroll
            for (int i = 0; i < 4; i++) {
                *reinterpret_cast<uint4*>(smem + SM_B_HI + doff + i * 16) =
                    *reinterpret_cast<const uint4*>(sh + i * 8);
                *reinterpret_cast<uint4*>(smem + SM_B_LO + doff + i * 16) =
                    *reinterpret_cast<const uint4*>(sl + i * 8);
            }
        }
        __syncthreads();

        float c[2][4][4];
#pragma unroll
        for (int mf = 0; mf < 2; mf++)
#pragma unroll
            for (int nf = 0; nf < 4; nf++)
#pragma unroll
                for (int q = 0; q < 4; q++) c[mf][nf][q] = 0.f;

#pragma unroll
        for (int kt = 0; kt < 8; kt++) {
            uint32_t ah[2][4], al[2][4], bh[2][4], bl[2][4];
            ldsm_x4(ah[0], aAddr + kt * 32);
            ldsm_x4(ah[1], aAddr + 16 * AST + kt * 32);
            ldsm_x4(al[0], aAddr + SM_A_LO + kt * 32);
            ldsm_x4(al[1], aAddr + SM_A_LO + 16 * AST + kt * 32);
            ldsm_x4(bh[0], bAddr + kt * 32);
            ldsm_x4(bh[1], bAddr + 16 * AST + kt * 32);
            ldsm_x4(bl[0], bAddr + (SM_B_LO - SM_B_HI) + kt * 32);
            ldsm_x4(bl[1], bAddr + (SM_B_LO - SM_B_HI) + 16 * AST + kt * 32);
#pragma unroll
            for (int mf = 0; mf < 2; mf++)
#pragma unroll
                for (int nf = 0; nf < 4; nf++) {
                    int nh = nf >> 1, o = (nf & 1) * 2;
                    MMA_BF16(c[mf][nf], ah[mf], bh[nh][o], bh[nh][o + 1]);
                    MMA_BF16(c[mf][nf], ah[mf], bl[nh][o], bl[nh][o + 1]);
                    MMA_BF16(c[mf][nf], al[mf], bh[nh][o], bh[nh][o + 1]);
                }
        }

        // ---- epilogue: direct routed float2 stores ----
#pragma unroll
        for (int mf = 0; mf < 2; mf++) {
            int r0 = blockIdx.x * 128 + warpM * 32 + mf * 16 + (lane >> 2);
#pragma unroll
            for (int nf = 0; nf < 4; nf++) {
                int colL = warpN * 32 + nf * 8 + (lane & 3) * 2;
                int j = nt * 64 + colL;
                float2 v01 = make_float2(c[mf][nf][0], c[mf][nf][1]);
                float2 v23 = make_float2(c[mf][nf][2], c[mf][nf][3]);
                if (j < D) {
                    if (r0 < NN)     *reinterpret_cast<float2*>(g_z + (size_t)r0 * D + j) = v01;
                    if (r0 + 8 < NN) *reinterpret_cast<float2*>(g_z + (size_t)(r0 + 8) * D + j) = v23;
                } else {
                    int oc = j - D;
                    if (r0 < NN)     *reinterpret_cast<float2*>(out + (size_t)r0 * (H * D) + oc) = v01;
                    if (r0 + 8 < NN) *reinterpret_cast<float2*>(out + (size_t)(r0 + 8) * (H * D) + oc) = v23;
                }
            }
        }
        __syncthreads();
    }
}

// ---------------------------------------------------------------------------
// GEMM2 (f32x2): st[N,160] = z[N,64] @ Wst[64,192(pad)]
// ---------------------------------------------------------------------------
#define BM 128
#define BN 64
#define BK 16

__global__ __launch_bounds__(256) void gemm2_kernel() {
    __shared__ __align__(16) float As[2][BK][BM + 4];
    __shared__ __align__(16) float Bs[2][BK][BN];
    const int tid = threadIdx.x;
    const int tx = tid & 15, ty = tid >> 4;
    const int rowBase = blockIdx.y * BM;
    const int colBase = blockIdx.x * BN;
    const int aRow = tid >> 1;
    const int aK   = (tid & 1) << 3;
    const int bK   = tid >> 4;
    const int bCol = (tid & 15) << 2;
    const int gr   = rowBase + aRow;
    const bool aOk = (gr < NN);
    const float* aBase = g_z + (size_t)(aOk ? gr : 0) * D + aK;
    const float* bBase = g_Wst + (size_t)bK * WSTLD + colBase + bCol;
    const int NIT = D / BK;

    unsigned long long acc2[4][4];
#pragma unroll
    for (int i = 0; i < 4; i++)
#pragma unroll
        for (int j = 0; j < 4; j++) acc2[i][j] = 0ull;

    float4 ra0 = make_float4(0.f, 0.f, 0.f, 0.f), ra1 = ra0;
    if (aOk) {
        ra0 = *reinterpret_cast<const float4*>(aBase);
        ra1 = *reinterpret_cast<const float4*>(aBase + 4);
    }
    float4 rb = *reinterpret_cast<const float4*>(bBase);
    As[0][aK + 0][aRow] = ra0.x; As[0][aK + 1][aRow] = ra0.y;
    As[0][aK + 2][aRow] = ra0.z; As[0][aK + 3][aRow] = ra0.w;
    As[0][aK + 4][aRow] = ra1.x; As[0][aK + 5][aRow] = ra1.y;
    As[0][aK + 6][aRow] = ra1.z; As[0][aK + 7][aRow] = ra1.w;
    *reinterpret_cast<float4*>(&Bs[0][bK][bCol]) = rb;
    __syncthreads();

#pragma unroll
    for (int it = 0; it < 4; it++) {
        const int buf = it & 1;
        float4 na0 = make_float4(0.f, 0.f, 0.f, 0.f), na1 = na0, nb = na0;
        if (it + 1 < NIT) {
            int k0 = (it + 1) * BK;
            if (aOk) {
                na0 = *reinterpret_cast<const float4*>(aBase + k0);
                na1 = *reinterpret_cast<const float4*>(aBase + k0 + 4);
            }
            nb = *reinterpret_cast<const float4*>(bBase + (size_t)k0 * WSTLD);
        }
#pragma unroll
        for (int kk = 0; kk < BK; kk++) {
            ulonglong2 A01 = *reinterpret_cast<const ulonglong2*>(&As[buf][kk][ty * 8]);
            ulonglong2 A23 = *reinterpret_cast<const ulonglong2*>(&As[buf][kk][ty * 8 + 4]);
            float4 b4 = *reinterpret_cast<const float4*>(&Bs[buf][kk][tx * 4]);
            unsigned long long bb[4];
            BCAST_F32X2(bb[0], b4.x); BCAST_F32X2(bb[1], b4.y);
            BCAST_F32X2(bb[2], b4.z); BCAST_F32X2(bb[3], b4.w);
#pragma unroll
            for (int j = 0; j < 4; j++) {
                FMA_F32X2(acc2[0][j], A01.x, bb[j]);
                FMA_F32X2(acc2[1][j], A01.y, bb[j]);
                FMA_F32X2(acc2[2][j], A23.x, bb[j]);
                FMA_F32X2(acc2[3][j], A23.y, bb[j]);
            }
        }
        if (it + 1 < NIT) {
            const int nbuf = buf ^ 1;
            As[nbuf][aK + 0][aRow] = na0.x; As[nbuf][aK + 1][aRow] = na0.y;
            As[nbuf][aK + 2][aRow] = na0.z; As[nbuf][aK + 3][aRow] = na0.w;
            As[nbuf][aK + 4][aRow] = na1.x; As[nbuf][aK + 5][aRow] = na1.y;
            As[nbuf][aK + 6][aRow] = na1.z; As[nbuf][aK + 7][aRow] = na1.w;
            *reinterpret_cast<float4*>(&Bs[nbuf][bK][bCol]) = nb;
            __syncthreads();
        }
    }

#pragma unroll
    for (int ip = 0; ip < 4; ip++) {
        float2 c0 = *reinterpret_cast<float2*>(&acc2[ip][0]);
        float2 c1 = *reinterpret_cast<float2*>(&acc2[ip][1]);
        float2 c2 = *reinterpret_cast<float2*>(&acc2[ip][2]);
        float2 c3 = *reinterpret_cast<float2*>(&acc2[ip][3]);
        int row0 = rowBase + ty * 8 + ip * 2;
        int col = colBase + tx * 4;
        if (col >= STCOLS) continue;
        float4 lo = make_float4(c0.x, c1.x, c2.x, c3.x);
        float4 hi = make_float4(c0.y, c1.y, c2.y, c3.y);
        if (row0 < NN)     *reinterpret_cast<float4*>(g_st + (size_t)row0 * STCOLS + col) = lo;
        if (row0 + 1 < NN) *reinterpret_cast<float4*>(g_st + (size_t)(row0 + 1) * STCOLS + col) = hi;
    }
}

// ---------------------------------------------------------------------------
// CSR build
// ---------------------------------------------------------------------------
__global__ void zero_deg_kernel() {
    int i = blockIdx.x * blockDim.x + threadIdx.x;
    if (i < NN) g_deg[i] = 0;
}

__global__ void hist_kernel(const int* __restrict__ dst) {
    int t = blockIdx.x * blockDim.x + threadIdx.x;
    if (t * 4 >= EE) return;
    int4 d4 = *reinterpret_cast<const int4*>(dst + t * 4);
    atomicAdd(&g_deg[d4.x], 1);
    atomicAdd(&g_deg[d4.y], 1);
    atomicAdd(&g_deg[d4.z], 1);
    atomicAdd(&g_deg[d4.w], 1);
}

#define SCAN_T 1024
#define SCAN_CHUNK 49
__global__ __launch_bounds__(SCAN_T) void scan_kernel() {
    __shared__ int sums[SCAN_T];
    int t = threadIdx.x;
    int beg = t * SCAN_CHUNK;
    int end = min(NN, beg + SCAN_CHUNK);
    int s = 0;
    for (int i = beg; i < end; i++) s += g_deg[i];
    sums[t] = s;
    __syncthreads();
#pragma unroll
    for (int off = 1; off < SCAN_T; off <<= 1) {
        int v = (t >= off) ? sums[t - off] : 0;
        __syncthreads();
        sums[t] += v;
        __syncthreads();
    }
    int run = (t == 0) ? 0 : sums[t - 1];
    for (int i = beg; i < end; i++) {
        g_rowptr[i] = run;
        g_cursor[i] = run;
        run += g_deg[i];
    }
    if (t == SCAN_T - 1) g_rowptr[NN] = sums[SCAN_T - 1];
}

__global__ void scatter_kernel(const int* __restrict__ src,
                               const int* __restrict__ dst,
                               const int* __restrict__ rel) {
    int e = blockIdx.x * blockDim.x + threadIdx.x;
    if (e >= EE) return;
    int d = dst[e];
    int pos = atomicAdd(&g_cursor[d], 1);
    g_csr[pos] = (unsigned)src[e] | ((unsigned)rel[e] << 16);
}

// ---------------------------------------------------------------------------
// Aggregate: one warp per destination node, 4-edge unrolled.
// ---------------------------------------------------------------------------
__global__ __launch_bounds__(256) void aggregate_kernel(float* __restrict__ out) {
    int w = (blockIdx.x * blockDim.x + threadIdx.x) >> 5;
    if (w >= NN) return;
    int lane = threadIdx.x & 31;

    int beg = g_rowptr[w];
    int end = g_rowptr[w + 1];

    float acc[8];
#pragma unroll
    for (int i = 0; i < 8; i++) acc[i] = 0.f;

    const float* tvb = g_st + (size_t)w * STCOLS + 80;
    const int zoff = lane << 1;

    int i = beg;
    for (; i + 3 < end; i += 4) {
        unsigned p0 = __ldg(&g_csr[i]);
        unsigned p1 = __ldg(&g_csr[i + 1]);
        unsigned p2 = __ldg(&g_csr[i + 2]);
        unsigned p3 = __ldg(&g_csr[i + 3]);
        int s0 = p0 & 0xFFFFu, r0 = p0 >> 16;
        int s1 = p1 & 0xFFFFu, r1 = p1 >> 16;
        int s2 = p2 & 0xFFFFu, r2 = p2 >> 16;
        int s3 = p3 & 0xFFFFu, r3 = p3 >> 16;
        float4 sv0 = *reinterpret_cast<const float4*>(g_st + (size_t)s0 * STCOLS + (r0 << 2));
        float4 sv1 = *reinterpret_cast<const float4*>(g_st + (size_t)s1 * STCOLS + (r1 << 2));
        float4 sv2 = *reinterpret_cast<const float4*>(g_st + (size_t)s2 * STCOLS + (r2 << 2));
        float4 sv3 = *reinterpret_cast<const float4*>(g_st + (size_t)s3 * STCOLS + (r3 << 2));
        float4 tv0 = *reinterpret_cast<const float4*>(tvb + (r0 << 2));
        float4 tv1 = *reinterpret_cast<const float4*>(tvb + (r1 << 2));
        float4 tv2 = *reinterpret_cast<const float4*>(tvb + (r2 << 2));
        float4 tv3 = *reinterpret_cast<const float4*>(tvb + (r3 << 2));
        float2 z0 = *reinterpret_cast<const float2*>(g_z + (size_t)s0 * D + zoff);
        float2 z1 = *reinterpret_cast<const float2*>(g_z + (size_t)s1 * D + zoff);
        float2 z2 = *reinterpret_cast<const float2*>(g_z + (size_t)s2 * D + zoff);
        float2 z3 = *reinterpret_cast<const float2*>(g_z + (size_t)s3 * D + zoff);

#define EDGE_ACC(sv, tv, zv)                                            \
        {                                                               \
            float a0 = sv.x + tv.x, a1 = sv.y + tv.y;                   \
            float a2 = sv.z + tv.z, a3 = sv.w + tv.w;                   \
            a0 = fmaxf(a0, 0.01f * a0); a1 = fmaxf(a1, 0.01f * a1);     \
            a2 = fmaxf(a2, 0.01f * a2); a3 = fmaxf(a3, 0.01f * a3);     \
            acc[0] += a0 * zv.x; acc[1] += a0 * zv.y;                   \
            acc[2] += a1 * zv.x; acc[3] += a1 * zv.y;                   \
            acc[4] += a2 * zv.x; acc[5] += a2 * zv.y;                   \
            acc[6] += a3 * zv.x; acc[7] += a3 * zv.y;                   \
        }
        EDGE_ACC(sv0, tv0, z0)
        EDGE_ACC(sv1, tv1, z1)
        EDGE_ACC(sv2, tv2, z2)
        EDGE_ACC(sv3, tv3, z3)
    }
    for (; i < end; i++) {
        unsigned pc = __ldg(&g_csr[i]);
        int s = pc & 0xFFFFu, r = pc >> 16;
        float4 sv = *reinterpret_cast<const float4*>(g_st + (size_t)s * STCOLS + (r << 2));
        float4 tv = *reinterpret_cast<const float4*>(tvb + (r << 2));
        float2 zv = *reinterpret_cast<const float2*>(g_z + (size_t)s * D + zoff);
        EDGE_ACC(sv, tv, zv)
    }
#undef EDGE_ACC

    float* o = out + (size_t)w * (H * D) + zoff;
#pragma unroll
    for (int hh = 0; hh < H; hh++) {
        float2* op = reinterpret_cast<float2*>(o + hh * D);
        float2 cur = *op;
        cur.x += acc[hh * 2 + 0];
        cur.y += acc[hh * 2 + 1];
        *op = cur;
    }
}

// ---------------------------------------------------------------------------
extern "C" void kernel_launch(void* const* d_in, const int* in_sizes, int n_in,
                              void* d_out, int out_size) {
    const float* h_in      = (const float*)d_in[0];
    const float* fc_w      = (const float*)d_in[1];
    const float* self_fc_w = (const float*)d_in[2];
    const float* attn_w    = (const float*)d_in[3];
    const float* w_comp    = (const float*)d_in[4];
    const int*   src       = (const int*)d_in[5];
    const int*   dst       = (const int*)d_in[6];
    const int*   rel       = (const int*)d_in[7];
    float* out = (float*)d_out;

    cudaFuncSetAttribute(tc_gemm1_kernel,
                         cudaFuncAttributeMaxDynamicSharedMemorySize, SM_TOT);

    build_wst_kernel<<<(D * WSTLD + 255) / 256, 256>>>(w_comp, attn_w);
    build_w1bf16_kernel<<<(W1COLS * INDIM + 255) / 256, 256>>>(fc_w, self_fc_w);

    zero_deg_kernel<<<(NN + 255) / 256, 256>>>();
    hist_kernel<<<(EE / 4 + 255) / 256, 256>>>(dst);
    scan_kernel<<<1, SCAN_T>>>();
    scatter_kernel<<<(EE + 255) / 256, 256>>>(src, dst, rel);

    tc_gemm1_kernel<<<(NN + 127) / 128, 256, SM_TOT>>>(h_in, out);

    dim3 g2(WSTLD / BN, (NN + BM - 1) / BM);
    gemm2_kernel<<<g2, 256>>>();

    aggregate_kernel<<<(NN * 32 + 255) / 256, 256>>>(out);
}

// round 16
// speedup vs baseline: 1.1309x; 1.0083x over previous
#include <cuda_runtime.h>
#include <cuda_bf16.h>
#include <cstdint>

#define NN      50000
#define EE      800000
#define INDIM   128
#define D       64
#define H       4
#define NR      20
#define NB      8
#define STCOLS  160
#define W1COLS  320
#define WSTLD   192

// ---- static scratch ----
__device__ __align__(16) float g_z[NN * D];
__device__ __align__(16) float g_st[NN * STCOLS];
__device__ __align__(16) __nv_bfloat16 g_zhi[NN * D];
__device__ __align__(16) __nv_bfloat16 g_zlo[NN * D];
__device__ __align__(16) __nv_bfloat16 g_Wsthi[WSTLD * D];  // [jj][c] transposed
__device__ __align__(16) __nv_bfloat16 g_Wstlo[WSTLD * D];
__device__ __align__(16) __nv_bfloat16 g_W1hi[W1COLS * INDIM];
__device__ __align__(16) __nv_bfloat16 g_W1lo[W1COLS * INDIM];
__device__ int g_deg[NN];
__device__ int g_rowptr[NN + 1];
__device__ int g_cursor[NN];
__device__ unsigned g_csr[EE];

__device__ __forceinline__ uint32_t smem_u32(const void* p) {
    uint32_t a;
    asm("{ .reg .u64 t; cvta.to.shared.u64 t, %1; cvt.u32.u64 %0, t; }" : "=r"(a) : "l"(p));
    return a;
}
__device__ __forceinline__ void ldsm_x4(uint32_t* r, uint32_t addr) {
    asm volatile("ldmatrix.sync.aligned.m8n8.x4.shared.b16 {%0,%1,%2,%3}, [%4];"
                 : "=r"(r[0]), "=r"(r[1]), "=r"(r[2]), "=r"(r[3]) : "r"(addr));
}
#define MMA_BF16(c, a, b0, b1)                                                   \
    asm volatile("mma.sync.aligned.m16n8k16.row.col.f32.bf16.bf16.f32 "          \
                 "{%0,%1,%2,%3}, {%4,%5,%6,%7}, {%8,%9}, {%0,%1,%2,%3};"         \
                 : "+f"((c)[0]), "+f"((c)[1]), "+f"((c)[2]), "+f"((c)[3])        \
                 : "r"((a)[0]), "r"((a)[1]), "r"((a)[2]), "r"((a)[3]),           \
                   "r"(b0), "r"(b1))

__device__ __forceinline__ uint32_t pack_bf16x2(float a, float b) {
    unsigned short ua = __bfloat16_as_ushort(__float2bfloat16_rn(a));
    unsigned short ub = __bfloat16_as_ushort(__float2bfloat16_rn(b));
    return (uint32_t)ua | ((uint32_t)ub << 16);
}

// ---------------------------------------------------------------------------
// Wst basis combination, emitted directly as bf16 hi/lo TRANSPOSED [jj][c]
// (B operand rows: n-major, k contiguous). Pad jj>=160 zeroed.
// ---------------------------------------------------------------------------
__global__ void build_wst_kernel(const float* __restrict__ w_comp,
                                 const float* __restrict__ aw) {
    int idx = blockIdx.x * blockDim.x + threadIdx.x;
    if (idx >= D * WSTLD) return;
    int c  = idx / WSTLD;
    int jj = idx % WSTLD;
    float acc = 0.f;
    if (jj < STCOLS) {
        int r, hh, cc;
        if (jj < 80) { r = jj >> 2; hh = jj & 3; cc = c; }
        else         { int j2 = jj - 80; r = j2 >> 2; hh = j2 & 3; cc = c + D; }
#pragma unroll
        for (int b = 0; b < NB; b++)
            acc += w_comp[r * NB + b] * aw[b * (2 * D * H) + cc * H + hh];
    }
    __nv_bfloat16 hi = __float2bfloat16_rn(acc);
    g_Wsthi[jj * D + c] = hi;
    g_Wstlo[jj * D + c] = __float2bfloat16_rn(acc - __bfloat162float(hi));
}

// split W1 (fc^T rows then self^T rows) into bf16 hi/lo, [320][128] row-major
__global__ void build_w1bf16_kernel(const float* __restrict__ fc_w,
                                    const float* __restrict__ self_fc_w) {
    int idx = blockIdx.x * blockDim.x + threadIdx.x;
    if (idx >= W1COLS * INDIM) return;
    int j = idx >> 7, k = idx & 127;
    float w = (j < D) ? fc_w[j * INDIM + k] : self_fc_w[(j - D) * INDIM + k];
    __nv_bfloat16 hi = __float2bfloat16_rn(w);
    g_W1hi[idx] = hi;
    g_W1lo[idx] = __float2bfloat16_rn(w - __bfloat162float(hi));
}

// ---------------------------------------------------------------------------
// GEMM1: mma.sync bf16 3-split. CTA 128 rows x 320 cols (5 tiles of 64).
// z cols additionally emitted as bf16 hi/lo for GEMM2.
// ---------------------------------------------------------------------------
#define AST      272
#define SM_A_HI  0
#define SM_A_LO  34816
#define SM_B_HI  69632
#define SM_B_LO  87040
#define SM_TOT   104448

__global__ __launch_bounds__(256, 1) void tc_gemm1_kernel(
    const float* __restrict__ A, float* __restrict__ out) {
    extern __shared__ __align__(16) char smem[];
    const uint32_t sb = smem_u32(smem);
    const int tid = threadIdx.x;
    const int lane = tid & 31;
    const int wid = tid >> 5;

    // ---- A conversion ----
    {
        int row = tid >> 1;
        int kh  = (tid & 1) << 6;
        int gr  = blockIdx.x * 128 + row;
        bool ok = gr < NN;
        const float* ap = A + (size_t)(ok ? gr : 0) * INDIM + kh;
#pragma unroll
        for (int g8 = 0; g8 < 8; g8++) {
            int k = kh + g8 * 8;
            float v[8];
            if (ok) {
                float4 v0 = *reinterpret_cast<const float4*>(ap + g8 * 8);
                float4 v1 = *reinterpret_cast<const float4*>(ap + g8 * 8 + 4);
                v[0]=v0.x; v[1]=v0.y; v[2]=v0.z; v[3]=v0.w;
                v[4]=v1.x; v[5]=v1.y; v[6]=v1.z; v[7]=v1.w;
            } else {
#pragma unroll
                for (int i = 0; i < 8; i++) v[i] = 0.f;
            }
            uint32_t hi[4], lo[4];
#pragma unroll
            for (int p = 0; p < 4; p++) {
                float h0 = __bfloat162float(__float2bfloat16_rn(v[p*2]));
                float h1 = __bfloat162float(__float2bfloat16_rn(v[p*2+1]));
                hi[p] = pack_bf16x2(v[p*2], v[p*2+1]);
                lo[p] = pack_bf16x2(v[p*2] - h0, v[p*2+1] - h1);
            }
            uint32_t off = (uint32_t)row * AST + k * 2;
            *reinterpret_cast<uint4*>(smem + SM_A_HI + off) = make_uint4(hi[0],hi[1],hi[2],hi[3]);
            *reinterpret_cast<uint4*>(smem + SM_A_LO + off) = make_uint4(lo[0],lo[1],lo[2],lo[3]);
        }
    }
    __syncthreads();

    const int warpM = wid & 3;
    const int warpN = wid >> 2;
    const int arow = (lane & 7) + ((lane >> 3) & 1) * 8;
    const int akb  = (lane >> 4) * 8;
    const int brow = (lane & 7) + ((lane >> 4) & 1) * 8;
    const int bkb  = ((lane >> 3) & 1) * 8;
    const uint32_t aAddr = sb + SM_A_HI + (uint32_t)(warpM * 32 + arow) * AST + akb * 2;
    const uint32_t bAddr = sb + SM_B_HI + (uint32_t)(warpN * 32 + brow) * AST + bkb * 2;

    for (int nt = 0; nt < 5; nt++) {
        {
            int n  = tid >> 2;
            int kq = (tid & 3) << 5;
            const __nv_bfloat16* sh = g_W1hi + (size_t)(nt * 64 + n) * INDIM + kq;
            const __nv_bfloat16* sl = g_W1lo + (size_t)(nt * 64 + n) * INDIM + kq;
            uint32_t doff = (uint32_t)n * AST + kq * 2;
#pragma unroll
            for (int i = 0; i < 4; i++) {
                *reinterpret_cast<uint4*>(smem + SM_B_HI + doff + i * 16) =
                    *reinterpret_cast<const uint4*>(sh + i * 8);
                *reinterpret_cast<uint4*>(smem + SM_B_LO + doff + i * 16) =
                    *reinterpret_cast<const uint4*>(sl + i * 8);
            }
        }
        __syncthreads();

        float c[2][4][4];
#pragma unroll
        for (int mf = 0; mf < 2; mf++)
#pragma unroll
            for (int nf = 0; nf < 4; nf++)
#pragma unroll
                for (int q = 0; q < 4; q++) c[mf][nf][q] = 0.f;

#pragma unroll
        for (int kt = 0; kt < 8; kt++) {
            uint32_t ah[2][4], al[2][4], bh[2][4], bl[2][4];
            ldsm_x4(ah[0], aAddr + kt * 32);
            ldsm_x4(ah[1], aAddr + 16 * AST + kt * 32);
            ldsm_x4(al[0], aAddr + SM_A_LO + kt * 32);
            ldsm_x4(al[1], aAddr + SM_A_LO + 16 * AST + kt * 32);
            ldsm_x4(bh[0], bAddr + kt * 32);
            ldsm_x4(bh[1], bAddr + 16 * AST + kt * 32);
            ldsm_x4(bl[0], bAddr + (SM_B_LO - SM_B_HI) + kt * 32);
            ldsm_x4(bl[1], bAddr + (SM_B_LO - SM_B_HI) + 16 * AST + kt * 32);
#pragma unroll
            for (int mf = 0; mf < 2; mf++)
#pragma unroll
                for (int nf = 0; nf < 4; nf++) {
                    int nh = nf >> 1, o = (nf & 1) * 2;
                    MMA_BF16(c[mf][nf], ah[mf], bh[nh][o], bh[nh][o + 1]);
                    MMA_BF16(c[mf][nf], ah[mf], bl[nh][o], bl[nh][o + 1]);
                    MMA_BF16(c[mf][nf], al[mf], bh[nh][o], bh[nh][o + 1]);
                }
        }

        // ---- epilogue ----
#pragma unroll
        for (int mf = 0; mf < 2; mf++) {
            int r0 = blockIdx.x * 128 + warpM * 32 + mf * 16 + (lane >> 2);
#pragma unroll
            for (int nf = 0; nf < 4; nf++) {
                int colL = warpN * 32 + nf * 8 + (lane & 3) * 2;
                int j = nt * 64 + colL;
                float2 v01 = make_float2(c[mf][nf][0], c[mf][nf][1]);
                float2 v23 = make_float2(c[mf][nf][2], c[mf][nf][3]);
                if (j < D) {
                    if (r0 < NN) {
                        *reinterpret_cast<float2*>(g_z + (size_t)r0 * D + j) = v01;
                        uint32_t h = pack_bf16x2(v01.x, v01.y);
                        float h0 = __bfloat162float(__float2bfloat16_rn(v01.x));
                        float h1 = __bfloat162float(__float2bfloat16_rn(v01.y));
                        uint32_t l = pack_bf16x2(v01.x - h0, v01.y - h1);
                        *reinterpret_cast<uint32_t*>(g_zhi + (size_t)r0 * D + j) = h;
                        *reinterpret_cast<uint32_t*>(g_zlo + (size_t)r0 * D + j) = l;
                    }
                    if (r0 + 8 < NN) {
                        *reinterpret_cast<float2*>(g_z + (size_t)(r0 + 8) * D + j) = v23;
                        uint32_t h = pack_bf16x2(v23.x, v23.y);
                        float h0 = __bfloat162float(__float2bfloat16_rn(v23.x));
                        float h1 = __bfloat162float(__float2bfloat16_rn(v23.y));
                        uint32_t l = pack_bf16x2(v23.x - h0, v23.y - h1);
                        *reinterpret_cast<uint32_t*>(g_zhi + (size_t)(r0 + 8) * D + j) = h;
                        *reinterpret_cast<uint32_t*>(g_zlo + (size_t)(r0 + 8) * D + j) = l;
                    }
                } else {
                    int oc = j - D;
                    if (r0 < NN)     *reinterpret_cast<float2*>(out + (size_t)r0 * (H * D) + oc) = v01;
                    if (r0 + 8 < NN) *reinterpret_cast<float2*>(out + (size_t)(r0 + 8) * (H * D) + oc) = v23;
                }
            }
        }
        __syncthreads();
    }
}

// ---------------------------------------------------------------------------
// GEMM2: st[N,160] = z[N,64] @ Wst^T via mma.sync bf16 3-split.
// A = g_zhi/g_zlo (pre-split by GEMM1). B = g_Wsthi/lo [192][64].
// CTA 128 rows x 192 cols (3 tiles of 64), K=64 (4 k-steps).
// ---------------------------------------------------------------------------
#define AST2      144          // 64 bf16 = 128B padded to 144
#define SM2_A_HI  0
#define SM2_A_LO  18432        // 128*144
#define SM2_B_HI  36864
#define SM2_B_LO  46080        // + 64*144
#define SM2_TOT   55296

__global__ __launch_bounds__(256, 1) void tc_gemm2_kernel() {
    extern __shared__ __align__(16) char smem[];
    const uint32_t sb = smem_u32(smem);
    const int tid = threadIdx.x;
    const int lane = tid & 31;
    const int wid = tid >> 5;

    // ---- A load (already bf16): row = tid/2, 32 k values per thread ----
    {
        int row = tid >> 1;
        int kh  = (tid & 1) << 5;
        int gr  = blockIdx.x * 128 + row;
        bool ok = gr < NN;
        const __nv_bfloat16* sh = g_zhi + (size_t)(ok ? gr : 0) * D + kh;
        const __nv_bfloat16* sl = g_zlo + (size_t)(ok ? gr : 0) * D + kh;
        uint32_t doff = (uint32_t)row * AST2 + kh * 2;
#pragma unroll
        for (int i = 0; i < 4; i++) {
            *reinterpret_cast<uint4*>(smem + SM2_A_HI + doff + i * 16) =
                *reinterpret_cast<const uint4*>(sh + i * 8);
            *reinterpret_cast<uint4*>(smem + SM2_A_LO + doff + i * 16) =
                *reinterpret_cast<const uint4*>(sl + i * 8);
        }
    }
    __syncthreads();

    const int warpM = wid & 3;
    const int warpN = wid >> 2;
    const int arow = (lane & 7) + ((lane >> 3) & 1) * 8;
    const int akb  = (lane >> 4) * 8;
    const int brow = (lane & 7) + ((lane >> 4) & 1) * 8;
    const int bkb  = ((lane >> 3) & 1) * 8;
    const uint32_t aAddr = sb + SM2_A_HI + (uint32_t)(warpM * 32 + arow) * AST2 + akb * 2;
    const uint32_t bAddr = sb + SM2_B_HI + (uint32_t)(warpN * 32 + brow) * AST2 + bkb * 2;

    for (int nt = 0; nt < 3; nt++) {
        // ---- B tile: n = tid/4, 16 k values ----
        {
            int n  = tid >> 2;
            int kq = (tid & 3) << 4;
            const __nv_bfloat16* sh = g_Wsthi + (size_t)(nt * 64 + n) * D + kq;
            const __nv_bfloat16* sl = g_Wstlo + (size_t)(nt * 64 + n) * D + kq;
            uint32_t doff = (uint32_t)n * AST2 + kq * 2;
#pragma unroll
            for (int i = 0; i < 2; i++) {
                *reinterpret_cast<uint4*>(smem + SM2_B_HI + doff + i * 16) =
                    *reinterpret_cast<const uint4*>(sh + i * 8);
                *reinterpret_cast<uint4*>(smem + SM2_B_LO + doff + i * 16) =
                    *reinterpret_cast<const uint4*>(sl + i * 8);
            }
        }
        __syncthreads();

        float c[2][4][4];
#pragma unroll
        for (int mf = 0; mf < 2; mf++)
#pragma unroll
            for (int nf = 0; nf < 4; nf++)
#pragma unroll
                for (int q = 0; q < 4; q++) c[mf][nf][q] = 0.f;

#pragma unroll
        for (int kt = 0; kt < 4; kt++) {
            uint32_t ah[2][4], al[2][4], bh[2][4], bl[2][4];
            ldsm_x4(ah[0], aAddr + kt * 32);
            ldsm_x4(ah[1], aAddr + 16 * AST2 + kt * 32);
            ldsm_x4(al[0], aAddr + (SM2_A_LO - SM2_A_HI) + kt * 32);
            ldsm_x4(al[1], aAddr + (SM2_A_LO - SM2_A_HI) + 16 * AST2 + kt * 32);
            ldsm_x4(bh[0], bAddr + kt * 32);
            ldsm_x4(bh[1], bAddr + 16 * AST2 + kt * 32);
            ldsm_x4(bl[0], bAddr + (SM2_B_LO - SM2_B_HI) + kt * 32);
            ldsm_x4(bl[1], bAddr + (SM2_B_LO - SM2_B_HI) + 16 * AST2 + kt * 32);
#pragma unroll
            for (int mf = 0; mf < 2; mf++)
#pragma unroll
                for (int nf = 0; nf < 4; nf++) {
                    int nh = nf >> 1, o = (nf & 1) * 2;
                    MMA_BF16(c[mf][nf], ah[mf], bh[nh][o], bh[nh][o + 1]);
                    MMA_BF16(c[mf][nf], ah[mf], bl[nh][o], bl[nh][o + 1]);
                    MMA_BF16(c[mf][nf], al[mf], bh[nh][o], bh[nh][o + 1]);
                }
        }

#pragma unroll
        for (int mf = 0; mf < 2; mf++) {
            int r0 = blockIdx.x * 128 + warpM * 32 + mf * 16 + (lane >> 2);
#pragma unroll
            for (int nf = 0; nf < 4; nf++) {
                int colL = warpN * 32 + nf * 8 + (lane & 3) * 2;
                int j = nt * 64 + colL;
                if (j >= STCOLS) continue;
                float2 v01 = make_float2(c[mf][nf][0], c[mf][nf][1]);
                float2 v23 = make_float2(c[mf][nf][2], c[mf][nf][3]);
                if (r0 < NN)     *reinterpret_cast<float2*>(g_st + (size_t)r0 * STCOLS + j) = v01;
                if (r0 + 8 < NN) *reinterpret_cast<float2*>(g_st + (size_t)(r0 + 8) * STCOLS + j) = v23;
            }
        }
        __syncthreads();
    }
}

// ---------------------------------------------------------------------------
// CSR build
// ---------------------------------------------------------------------------
__global__ void zero_deg_kernel() {
    int i = blockIdx.x * blockDim.x + threadIdx.x;
    if (i < NN) g_deg[i] = 0;
}

__global__ void hist_kernel(const int* __restrict__ dst) {
    int t = blockIdx.x * blockDim.x + threadIdx.x;
    if (t * 4 >= EE) return;
    int4 d4 = *reinterpret_cast<const int4*>(dst + t * 4);
    atomicAdd(&g_deg[d4.x], 1);
    atomicAdd(&g_deg[d4.y], 1);
    atomicAdd(&g_deg[d4.z], 1);
    atomicAdd(&g_deg[d4.w], 1);
}

#define SCAN_T 1024
#define SCAN_CHUNK 49
__global__ __launch_bounds__(SCAN_T) void scan_kernel() {
    __shared__ int sums[SCAN_T];
    int t = threadIdx.x;
    int beg = t * SCAN_CHUNK;
    int end = min(NN, beg + SCAN_CHUNK);
    int s = 0;
    for (int i = beg; i < end; i++) s += g_deg[i];
    sums[t] = s;
    __syncthreads();
#pragma unroll
    for (int off = 1; off < SCAN_T; off <<= 1) {
        int v = (t >= off) ? sums[t - off] : 0;
        __syncthreads();
        sums[t] += v;
        __syncthreads();
    }
    int run = (t == 0) ? 0 : sums[t - 1];
    for (int i = beg; i < end; i++) {
        g_rowptr[i] = run;
        g_cursor[i] = run;
        run += g_deg[i];
    }
    if (t == SCAN_T - 1) g_rowptr[NN] = sums[SCAN_T - 1];
}

__global__ void scatter_kernel(const int* __restrict__ src,
                               const int* __restrict__ dst,
                               const int* __restrict__ rel) {
    int e = blockIdx.x * blockDim.x + threadIdx.x;
    if (e >= EE) return;
    int d = dst[e];
    int pos = atomicAdd(&g_cursor[d], 1);
    g_csr[pos] = (unsigned)src[e] | ((unsigned)rel[e] << 16);
}

// ---------------------------------------------------------------------------
// Aggregate: one warp per destination node, 4-edge unrolled with csr
// software prefetch (next group's packed entries load during current math).
// ---------------------------------------------------------------------------
__global__ __launch_bounds__(256) void aggregate_kernel(float* __restrict__ out) {
    int w = (blockIdx.x * blockDim.x + threadIdx.x) >> 5;
    if (w >= NN) return;
    int lane = threadIdx.x & 31;

    int beg = g_rowptr[w];
    int end = g_rowptr[w + 1];

    float acc[8];
#pragma unroll
    for (int i = 0; i < 8; i++) acc[i] = 0.f;

    const float* tvb = g_st + (size_t)w * STCOLS + 80;
    const int zoff = lane << 1;

    int i = beg;
    unsigned q0 = 0, q1 = 0, q2 = 0, q3 = 0;
    if (i + 3 < end) {
        q0 = __ldg(&g_csr[i]);     q1 = __ldg(&g_csr[i + 1]);
        q2 = __ldg(&g_csr[i + 2]); q3 = __ldg(&g_csr[i + 3]);
    }
    for (; i + 3 < end; ) {
        unsigned p0 = q0, p1 = q1, p2 = q2, p3 = q3;
        i += 4;
        if (i + 3 < end) {
            q0 = __ldg(&g_csr[i]);     q1 = __ldg(&g_csr[i + 1]);
            q2 = __ldg(&g_csr[i + 2]); q3 = __ldg(&g_csr[i + 3]);
        }
        int s0 = p0 & 0xFFFFu, r0 = p0 >> 16;
        int s1 = p1 & 0xFFFFu, r1 = p1 >> 16;
        int s2 = p2 & 0xFFFFu, r2 = p2 >> 16;
        int s3 = p3 & 0xFFFFu, r3 = p3 >> 16;
        float4 sv0 = *reinterpret_cast<const float4*>(g_st + (size_t)s0 * STCOLS + (r0 << 2));
        float4 sv1 = *reinterpret_cast<const float4*>(g_st + (size_t)s1 * STCOLS + (r1 << 2));
        float4 sv2 = *reinterpret_cast<const float4*>(g_st + (size_t)s2 * STCOLS + (r2 << 2));
        float4 sv3 = *reinterpret_cast<const float4*>(g_st + (size_t)s3 * STCOLS + (r3 << 2));
        float4 tv0 = *reinterpret_cast<const float4*>(tvb + (r0 << 2));
        float4 tv1 = *reinterpret_cast<const float4*>(tvb + (r1 << 2));
        float4 tv2 = *reinterpret_cast<const float4*>(tvb + (r2 << 2));
        float4 tv3 = *reinterpret_cast<const float4*>(tvb + (r3 << 2));
        float2 z0 = *reinterpret_cast<const float2*>(g_z + (size_t)s0 * D + zoff);
        float2 z1 = *reinterpret_cast<const float2*>(g_z + (size_t)s1 * D + zoff);
        float2 z2 = *reinterpret_cast<const float2*>(g_z + (size_t)s2 * D + zoff);
        float2 z3 = *reinterpret_cast<const float2*>(g_z + (size_t)s3 * D + zoff);

#define EDGE_ACC(sv, tv, zv)                                            \
        {                                                               \
            float a0 = sv.x + tv.x, a1 = sv.y + tv.y;                   \
            float a2 = sv.z + tv.z, a3 = sv.w + tv.w;                   \
            a0 = fmaxf(a0, 0.01f * a0); a1 = fmaxf(a1, 0.01f * a1);     \
            a2 = fmaxf(a2, 0.01f * a2); a3 = fmaxf(a3, 0.01f * a3);     \
            acc[0] += a0 * zv.x; acc[1] += a0 * zv.y;                   \
            acc[2] += a1 * zv.x; acc[3] += a1 * zv.y;                   \
            acc[4] += a2 * zv.x; acc[5] += a2 * zv.y;                   \
            acc[6] += a3 * zv.x; acc[7] += a3 * zv.y;                   \
        }
        EDGE_ACC(sv0, tv0, z0)
        EDGE_ACC(sv1, tv1, z1)
        EDGE_ACC(sv2, tv2, z2)
        EDGE_ACC(sv3, tv3, z3)
    }
    for (; i < end; i++) {
        unsigned pc = __ldg(&g_csr[i]);
        int s = pc & 0xFFFFu, r = pc >> 16;
        float4 sv = *reinterpret_cast<const float4*>(g_st + (size_t)s * STCOLS + (r << 2));
        float4 tv = *reinterpret_cast<const float4*>(tvb + (r << 2));
        float2 zv = *reinterpret_cast<const float2*>(g_z + (size_t)s * D + zoff);
        EDGE_ACC(sv, tv, zv)
    }
#undef EDGE_ACC

    float* o = out + (size_t)w * (H * D) + zoff;
#pragma unroll
    for (int hh = 0; hh < H; hh++) {
        float2* op = reinterpret_cast<float2*>(o + hh * D);
        float2 cur = *op;
        cur.x += acc[hh * 2 + 0];
        cur.y += acc[hh * 2 + 1];
        *op = cur;
    }
}

// ---------------------------------------------------------------------------
extern "C" void kernel_launch(void* const* d_in, const int* in_sizes, int n_in,
                              void* d_out, int out_size) {
    const float* h_in      = (const float*)d_in[0];
    const float* fc_w      = (const float*)d_in[1];
    const float* self_fc_w = (const float*)d_in[2];
    const float* attn_w    = (const float*)d_in[3];
    const float* w_comp    = (const float*)d_in[4];
    const int*   src       = (const int*)d_in[5];
    const int*   dst       = (const int*)d_in[6];
    const int*   rel       = (const int*)d_in[7];
    float* out = (float*)d_out;

    cudaFuncSetAttribute(tc_gemm1_kernel,
                         cudaFuncAttributeMaxDynamicSharedMemorySize, SM_TOT);
    cudaFuncSetAttribute(tc_gemm2_kernel,
                         cudaFuncAttributeMaxDynamicSharedMemorySize, SM2_TOT);

    build_wst_kernel<<<(D * WSTLD + 255) / 256, 256>>>(w_comp, attn_w);
    build_w1bf16_kernel<<<(W1COLS * INDIM + 255) / 256, 256>>>(fc_w, self_fc_w);

    zero_deg_kernel<<<(NN + 255) / 256, 256>>>();
    hist_kernel<<<(EE / 4 + 255) / 256, 256>>>(dst);
    scan_kernel<<<1, SCAN_T>>>();
    scatter_kernel<<<(EE + 255) / 256, 256>>>(src, dst, rel);

    tc_gemm1_kernel<<<(NN + 127) / 128, 256, SM_TOT>>>(h_in, out);
    tc_gemm2_kernel<<<(NN + 127) / 128, 256, SM2_TOT>>>();

    aggregate_kernel<<<(NN * 32 + 255) / 256, 256>>>(out);
}

// round 17
// speedup vs baseline: 1.1751x; 1.0391x over previous
#include <cuda_runtime.h>
#include <cuda_bf16.h>
#include <cstdint>

#define NN      50000
#define EE      800000
#define INDIM   128
#define D       64
#define H       4
#define NR      20
#define NB      8
#define STCOLS  160
#define W1COLS  320
#define WSTLD   192

// ---- static scratch ----
__device__ __align__(16) float g_z[NN * D];
__device__ __align__(16) float g_st[NN * STCOLS];
__device__ __align__(16) __nv_bfloat16 g_zhi[NN * D];
__device__ __align__(16) __nv_bfloat16 g_zlo[NN * D];
__device__ __align__(16) __nv_bfloat16 g_Wsthi[WSTLD * D];  // [jj][c] transposed
__device__ __align__(16) __nv_bfloat16 g_Wstlo[WSTLD * D];
__device__ __align__(16) __nv_bfloat16 g_W1hi[W1COLS * INDIM];
__device__ __align__(16) __nv_bfloat16 g_W1lo[W1COLS * INDIM];
__device__ int g_deg[NN];
__device__ int g_rowptr[NN + 1];
__device__ int g_cursor[NN];
__device__ unsigned g_csr[EE];

__device__ __forceinline__ uint32_t smem_u32(const void* p) {
    uint32_t a;
    asm("{ .reg .u64 t; cvta.to.shared.u64 t, %1; cvt.u32.u64 %0, t; }" : "=r"(a) : "l"(p));
    return a;
}
__device__ __forceinline__ void ldsm_x4(uint32_t* r, uint32_t addr) {
    asm volatile("ldmatrix.sync.aligned.m8n8.x4.shared.b16 {%0,%1,%2,%3}, [%4];"
                 : "=r"(r[0]), "=r"(r[1]), "=r"(r[2]), "=r"(r[3]) : "r"(addr));
}
#define MMA_BF16(c, a, b0, b1)                                                   \
    asm volatile("mma.sync.aligned.m16n8k16.row.col.f32.bf16.bf16.f32 "          \
                 "{%0,%1,%2,%3}, {%4,%5,%6,%7}, {%8,%9}, {%0,%1,%2,%3};"         \
                 : "+f"((c)[0]), "+f"((c)[1]), "+f"((c)[2]), "+f"((c)[3])        \
                 : "r"((a)[0]), "r"((a)[1]), "r"((a)[2]), "r"((a)[3]),           \
                   "r"(b0), "r"(b1))

__device__ __forceinline__ uint32_t pack_bf16x2(float a, float b) {
    unsigned short ua = __bfloat16_as_ushort(__float2bfloat16_rn(a));
    unsigned short ub = __bfloat16_as_ushort(__float2bfloat16_rn(b));
    return (uint32_t)ua | ((uint32_t)ub << 16);
}

// ---------------------------------------------------------------------------
// Wst basis combination, emitted as bf16 hi/lo transposed [jj][c].
// ---------------------------------------------------------------------------
__global__ void build_wst_kernel(const float* __restrict__ w_comp,
                                 const float* __restrict__ aw) {
    int idx = blockIdx.x * blockDim.x + threadIdx.x;
    if (idx >= D * WSTLD) return;
    int c  = idx / WSTLD;
    int jj = idx % WSTLD;
    float acc = 0.f;
    if (jj < STCOLS) {
        int r, hh, cc;
        if (jj < 80) { r = jj >> 2; hh = jj & 3; cc = c; }
        else         { int j2 = jj - 80; r = j2 >> 2; hh = j2 & 3; cc = c + D; }
#pragma unroll
        for (int b = 0; b < NB; b++)
            acc += w_comp[r * NB + b] * aw[b * (2 * D * H) + cc * H + hh];
    }
    __nv_bfloat16 hi = __float2bfloat16_rn(acc);
    g_Wsthi[jj * D + c] = hi;
    g_Wstlo[jj * D + c] = __float2bfloat16_rn(acc - __bfloat162float(hi));
}

__global__ void build_w1bf16_kernel(const float* __restrict__ fc_w,
                                    const float* __restrict__ self_fc_w) {
    int idx = blockIdx.x * blockDim.x + threadIdx.x;
    if (idx >= W1COLS * INDIM) return;
    int j = idx >> 7, k = idx & 127;
    float w = (j < D) ? fc_w[j * INDIM + k] : self_fc_w[(j - D) * INDIM + k];
    __nv_bfloat16 hi = __float2bfloat16_rn(w);
    g_W1hi[idx] = hi;
    g_W1lo[idx] = __float2bfloat16_rn(w - __bfloat162float(hi));
}

// ---------------------------------------------------------------------------
// GEMM1: mma.sync bf16 3-split. CTA 128 rows x 320 cols (5 tiles of 64).
// ---------------------------------------------------------------------------
#define AST      272
#define SM_A_HI  0
#define SM_A_LO  34816
#define SM_B_HI  69632
#define SM_B_LO  87040
#define SM_TOT   104448

__global__ __launch_bounds__(256, 1) void tc_gemm1_kernel(
    const float* __restrict__ A, float* __restrict__ out) {
    extern __shared__ __align__(16) char smem[];
    const uint32_t sb = smem_u32(smem);
    const int tid = threadIdx.x;
    const int lane = tid & 31;
    const int wid = tid >> 5;

    {
        int row = tid >> 1;
        int kh  = (tid & 1) << 6;
        int gr  = blockIdx.x * 128 + row;
        bool ok = gr < NN;
        const float* ap = A + (size_t)(ok ? gr : 0) * INDIM + kh;
#pragma unroll
        for (int g8 = 0; g8 < 8; g8++) {
            int k = kh + g8 * 8;
            float v[8];
            if (ok) {
                float4 v0 = *reinterpret_cast<const float4*>(ap + g8 * 8);
                float4 v1 = *reinterpret_cast<const float4*>(ap + g8 * 8 + 4);
                v[0]=v0.x; v[1]=v0.y; v[2]=v0.z; v[3]=v0.w;
                v[4]=v1.x; v[5]=v1.y; v[6]=v1.z; v[7]=v1.w;
            } else {
#pragma unroll
                for (int i = 0; i < 8; i++) v[i] = 0.f;
            }
            uint32_t hi[4], lo[4];
#pragma unroll
            for (int p = 0; p < 4; p++) {
                float h0 = __bfloat162float(__float2bfloat16_rn(v[p*2]));
                float h1 = __bfloat162float(__float2bfloat16_rn(v[p*2+1]));
                hi[p] = pack_bf16x2(v[p*2], v[p*2+1]);
                lo[p] = pack_bf16x2(v[p*2] - h0, v[p*2+1] - h1);
            }
            uint32_t off = (uint32_t)row * AST + k * 2;
            *reinterpret_cast<uint4*>(smem + SM_A_HI + off) = make_uint4(hi[0],hi[1],hi[2],hi[3]);
            *reinterpret_cast<uint4*>(smem + SM_A_LO + off) = make_uint4(lo[0],lo[1],lo[2],lo[3]);
        }
    }
    __syncthreads();

    const int warpM = wid & 3;
    const int warpN = wid >> 2;
    const int arow = (lane & 7) + ((lane >> 3) & 1) * 8;
    const int akb  = (lane >> 4) * 8;
    const int brow = (lane & 7) + ((lane >> 4) & 1) * 8;
    const int bkb  = ((lane >> 3) & 1) * 8;
    const uint32_t aAddr = sb + SM_A_HI + (uint32_t)(warpM * 32 + arow) * AST + akb * 2;
    const uint32_t bAddr = sb + SM_B_HI + (uint32_t)(warpN * 32 + brow) * AST + bkb * 2;

    for (int nt = 0; nt < 5; nt++) {
        {
            int n  = tid >> 2;
            int kq = (tid & 3) << 5;
            const __nv_bfloat16* sh = g_W1hi + (size_t)(nt * 64 + n) * INDIM + kq;
            const __nv_bfloat16* sl = g_W1lo + (size_t)(nt * 64 + n) * INDIM + kq;
            uint32_t doff = (uint32_t)n * AST + kq * 2;
#pragma unroll
            for (int i = 0; i < 4; i++) {
                *reinterpret_cast<uint4*>(smem + SM_B_HI + doff + i * 16) =
                    *reinterpret_cast<const uint4*>(sh + i * 8);
                *reinterpret_cast<uint4*>(smem + SM_B_LO + doff + i * 16) =
                    *reinterpret_cast<const uint4*>(sl + i * 8);
            }
        }
        __syncthreads();

        float c[2][4][4];
#pragma unroll
        for (int mf = 0; mf < 2; mf++)
#pragma unroll
            for (int nf = 0; nf < 4; nf++)
#pragma unroll
                for (int q = 0; q < 4; q++) c[mf][nf][q] = 0.f;

#pragma unroll
        for (int kt = 0; kt < 8; kt++) {
            uint32_t ah[2][4], al[2][4], bh[2][4], bl[2][4];
            ldsm_x4(ah[0], aAddr + kt * 32);
            ldsm_x4(ah[1], aAddr + 16 * AST + kt * 32);
            ldsm_x4(al[0], aAddr + SM_A_LO + kt * 32);
            ldsm_x4(al[1], aAddr + SM_A_LO + 16 * AST + kt * 32);
            ldsm_x4(bh[0], bAddr + kt * 32);
            ldsm_x4(bh[1], bAddr + 16 * AST + kt * 32);
            ldsm_x4(bl[0], bAddr + (SM_B_LO - SM_B_HI) + kt * 32);
            ldsm_x4(bl[1], bAddr + (SM_B_LO - SM_B_HI) + 16 * AST + kt * 32);
#pragma unroll
            for (int mf = 0; mf < 2; mf++)
#pragma unroll
                for (int nf = 0; nf < 4; nf++) {
                    int nh = nf >> 1, o = (nf & 1) * 2;
                    MMA_BF16(c[mf][nf], ah[mf], bh[nh][o], bh[nh][o + 1]);
                    MMA_BF16(c[mf][nf], ah[mf], bl[nh][o], bl[nh][o + 1]);
                    MMA_BF16(c[mf][nf], al[mf], bh[nh][o], bh[nh][o + 1]);
                }
        }

#pragma unroll
        for (int mf = 0; mf < 2; mf++) {
            int r0 = blockIdx.x * 128 + warpM * 32 + mf * 16 + (lane >> 2);
#pragma unroll
            for (int nf = 0; nf < 4; nf++) {
                int colL = warpN * 32 + nf * 8 + (lane & 3) * 2;
                int j = nt * 64 + colL;
                float2 v01 = make_float2(c[mf][nf][0], c[mf][nf][1]);
                float2 v23 = make_float2(c[mf][nf][2], c[mf][nf][3]);
                if (j < D) {
                    if (r0 < NN) {
                        *reinterpret_cast<float2*>(g_z + (size_t)r0 * D + j) = v01;
                        uint32_t h = pack_bf16x2(v01.x, v01.y);
                        float h0 = __bfloat162float(__float2bfloat16_rn(v01.x));
                        float h1 = __bfloat162float(__float2bfloat16_rn(v01.y));
                        uint32_t l = pack_bf16x2(v01.x - h0, v01.y - h1);
                        *reinterpret_cast<uint32_t*>(g_zhi + (size_t)r0 * D + j) = h;
                        *reinterpret_cast<uint32_t*>(g_zlo + (size_t)r0 * D + j) = l;
                    }
                    if (r0 + 8 < NN) {
                        *reinterpret_cast<float2*>(g_z + (size_t)(r0 + 8) * D + j) = v23;
                        uint32_t h = pack_bf16x2(v23.x, v23.y);
                        float h0 = __bfloat162float(__float2bfloat16_rn(v23.x));
                        float h1 = __bfloat162float(__float2bfloat16_rn(v23.y));
                        uint32_t l = pack_bf16x2(v23.x - h0, v23.y - h1);
                        *reinterpret_cast<uint32_t*>(g_zhi + (size_t)(r0 + 8) * D + j) = h;
                        *reinterpret_cast<uint32_t*>(g_zlo + (size_t)(r0 + 8) * D + j) = l;
                    }
                } else {
                    int oc = j - D;
                    if (r0 < NN)     *reinterpret_cast<float2*>(out + (size_t)r0 * (H * D) + oc) = v01;
                    if (r0 + 8 < NN) *reinterpret_cast<float2*>(out + (size_t)(r0 + 8) * (H * D) + oc) = v23;
                }
            }
        }
        __syncthreads();
    }
}

// ---------------------------------------------------------------------------
// GEMM2: st[N,160] = z[N,64] @ Wst^T via mma.sync bf16 3-split.
// ---------------------------------------------------------------------------
#define AST2      144
#define SM2_A_HI  0
#define SM2_A_LO  18432
#define SM2_B_HI  36864
#define SM2_B_LO  46080
#define SM2_TOT   55296

__global__ __launch_bounds__(256, 1) void tc_gemm2_kernel() {
    extern __shared__ __align__(16) char smem[];
    const uint32_t sb = smem_u32(smem);
    const int tid = threadIdx.x;
    const int lane = tid & 31;
    const int wid = tid >> 5;

    {
        int row = tid >> 1;
        int kh  = (tid & 1) << 5;
        int gr  = blockIdx.x * 128 + row;
        bool ok = gr < NN;
        const __nv_bfloat16* sh = g_zhi + (size_t)(ok ? gr : 0) * D + kh;
        const __nv_bfloat16* sl = g_zlo + (size_t)(ok ? gr : 0) * D + kh;
        uint32_t doff = (uint32_t)row * AST2 + kh * 2;
#pragma unroll
        for (int i = 0; i < 4; i++) {
            *reinterpret_cast<uint4*>(smem + SM2_A_HI + doff + i * 16) =
                *reinterpret_cast<const uint4*>(sh + i * 8);
            *reinterpret_cast<uint4*>(smem + SM2_A_LO + doff + i * 16) =
                *reinterpret_cast<const uint4*>(sl + i * 8);
        }
    }
    __syncthreads();

    const int warpM = wid & 3;
    const int warpN = wid >> 2;
    const int arow = (lane & 7) + ((lane >> 3) & 1) * 8;
    const int akb  = (lane >> 4) * 8;
    const int brow = (lane & 7) + ((lane >> 4) & 1) * 8;
    const int bkb  = ((lane >> 3) & 1) * 8;
    const uint32_t aAddr = sb + SM2_A_HI + (uint32_t)(warpM * 32 + arow) * AST2 + akb * 2;
    const uint32_t bAddr = sb + SM2_B_HI + (uint32_t)(warpN * 32 + brow) * AST2 + bkb * 2;

    for (int nt = 0; nt < 3; nt++) {
        {
            int n  = tid >> 2;
            int kq = (tid & 3) << 4;
            const __nv_bfloat16* sh = g_Wsthi + (size_t)(nt * 64 + n) * D + kq;
            const __nv_bfloat16* sl = g_Wstlo + (size_t)(nt * 64 + n) * D + kq;
            uint32_t doff = (uint32_t)n * AST2 + kq * 2;
#pragma unroll
            for (int i = 0; i < 2; i++) {
                *reinterpret_cast<uint4*>(smem + SM2_B_HI + doff + i * 16) =
                    *reinterpret_cast<const uint4*>(sh + i * 8);
                *reinterpret_cast<uint4*>(smem + SM2_B_LO + doff + i * 16) =
                    *reinterpret_cast<const uint4*>(sl + i * 8);
            }
        }
        __syncthreads();

        float c[2][4][4];
#pragma unroll
        for (int mf = 0; mf < 2; mf++)
#pragma unroll
            for (int nf = 0; nf < 4; nf++)
#pragma unroll
                for (int q = 0; q < 4; q++) c[mf][nf][q] = 0.f;

#pragma unroll
        for (int kt = 0; kt < 4; kt++) {
            uint32_t ah[2][4], al[2][4], bh[2][4], bl[2][4];
            ldsm_x4(ah[0], aAddr + kt * 32);
            ldsm_x4(ah[1], aAddr + 16 * AST2 + kt * 32);
            ldsm_x4(al[0], aAddr + (SM2_A_LO - SM2_A_HI) + kt * 32);
            ldsm_x4(al[1], aAddr + (SM2_A_LO - SM2_A_HI) + 16 * AST2 + kt * 32);
            ldsm_x4(bh[0], bAddr + kt * 32);
            ldsm_x4(bh[1], bAddr + 16 * AST2 + kt * 32);
            ldsm_x4(bl[0], bAddr + (SM2_B_LO - SM2_B_HI) + kt * 32);
            ldsm_x4(bl[1], bAddr + (SM2_B_LO - SM2_B_HI) + 16 * AST2 + kt * 32);
#pragma unroll
            for (int mf = 0; mf < 2; mf++)
#pragma unroll
                for (int nf = 0; nf < 4; nf++) {
                    int nh = nf >> 1, o = (nf & 1) * 2;
                    MMA_BF16(c[mf][nf], ah[mf], bh[nh][o], bh[nh][o + 1]);
                    MMA_BF16(c[mf][nf], ah[mf], bl[nh][o], bl[nh][o + 1]);
                    MMA_BF16(c[mf][nf], al[mf], bh[nh][o], bh[nh][o + 1]);
                }
        }

#pragma unroll
        for (int mf = 0; mf < 2; mf++) {
            int r0 = blockIdx.x * 128 + warpM * 32 + mf * 16 + (lane >> 2);
#pragma unroll
            for (int nf = 0; nf < 4; nf++) {
                int colL = warpN * 32 + nf * 8 + (lane & 3) * 2;
                int j = nt * 64 + colL;
                if (j >= STCOLS) continue;
                float2 v01 = make_float2(c[mf][nf][0], c[mf][nf][1]);
                float2 v23 = make_float2(c[mf][nf][2], c[mf][nf][3]);
                if (r0 < NN)     *reinterpret_cast<float2*>(g_st + (size_t)r0 * STCOLS + j) = v01;
                if (r0 + 8 < NN) *reinterpret_cast<float2*>(g_st + (size_t)(r0 + 8) * STCOLS + j) = v23;
            }
        }
        __syncthreads();
    }
}

// ---------------------------------------------------------------------------
// CSR build
// ---------------------------------------------------------------------------
__global__ void zero_deg_kernel() {
    int i = blockIdx.x * blockDim.x + threadIdx.x;
    if (i < NN) g_deg[i] = 0;
}

__global__ void hist_kernel(const int* __restrict__ dst) {
    int t = blockIdx.x * blockDim.x + threadIdx.x;
    if (t * 4 >= EE) return;
    int4 d4 = *reinterpret_cast<const int4*>(dst + t * 4);
    atomicAdd(&g_deg[d4.x], 1);
    atomicAdd(&g_deg[d4.y], 1);
    atomicAdd(&g_deg[d4.z], 1);
    atomicAdd(&g_deg[d4.w], 1);
}

#define SCAN_T 1024
#define SCAN_CHUNK 49
__global__ __launch_bounds__(SCAN_T) void scan_kernel() {
    __shared__ int sums[SCAN_T];
    int t = threadIdx.x;
    int beg = t * SCAN_CHUNK;
    int end = min(NN, beg + SCAN_CHUNK);
    int s = 0;
    for (int i = beg; i < end; i++) s += g_deg[i];
    sums[t] = s;
    __syncthreads();
#pragma unroll
    for (int off = 1; off < SCAN_T; off <<= 1) {
        int v = (t >= off) ? sums[t - off] : 0;
        __syncthreads();
        sums[t] += v;
        __syncthreads();
    }
    int run = (t == 0) ? 0 : sums[t - 1];
    for (int i = beg; i < end; i++) {
        g_rowptr[i] = run;
        g_cursor[i] = run;
        run += g_deg[i];
    }
    if (t == SCAN_T - 1) g_rowptr[NN] = sums[SCAN_T - 1];
}

__global__ void scatter_kernel(const int* __restrict__ src,
                               const int* __restrict__ dst,
                               const int* __restrict__ rel) {
    int e = blockIdx.x * blockDim.x + threadIdx.x;
    if (e >= EE) return;
    int d = dst[e];
    int pos = atomicAdd(&g_cursor[d], 1);
    g_csr[pos] = (unsigned)src[e] | ((unsigned)rel[e] << 16);
}

// ---------------------------------------------------------------------------
// Aggregate: TWO nodes per warp (16 lanes each). Lane l4 = lane&15 covers z
// cols [l4*4, l4*4+4). 2-edge unroll per half-warp => up to 4 edges in
// flight per warp. Non-atomic += into d_out.
// ---------------------------------------------------------------------------
__global__ __launch_bounds__(256) void aggregate_kernel(float* __restrict__ out) {
    int gw = (blockIdx.x * blockDim.x + threadIdx.x) >> 5;   // warp id
    int lane = threadIdx.x & 31;
    int half = lane >> 4;
    int l4   = lane & 15;
    int w = gw * 2 + half;          // NN = 50000 even; gw < 25000 -> w < NN
    if (gw >= NN / 2) return;

    int beg = g_rowptr[w];
    int end = g_rowptr[w + 1];

    float acc[16];                  // [head][4 cols]
#pragma unroll
    for (int i = 0; i < 16; i++) acc[i] = 0.f;

    const float* tvb = g_st + (size_t)w * STCOLS + 80;
    const int zcol = l4 << 2;

    int i = beg;
    for (; i + 1 < end; i += 2) {
        unsigned p0 = __ldg(&g_csr[i]);
        unsigned p1 = __ldg(&g_csr[i + 1]);
        int s0 = p0 & 0xFFFFu, r0 = p0 >> 16;
        int s1 = p1 & 0xFFFFu, r1 = p1 >> 16;
        float4 sv0 = *reinterpret_cast<const float4*>(g_st + (size_t)s0 * STCOLS + (r0 << 2));
        float4 sv1 = *reinterpret_cast<const float4*>(g_st + (size_t)s1 * STCOLS + (r1 << 2));
        float4 tv0 = *reinterpret_cast<const float4*>(tvb + (r0 << 2));
        float4 tv1 = *reinterpret_cast<const float4*>(tvb + (r1 << 2));
        float4 z0 = *reinterpret_cast<const float4*>(g_z + (size_t)s0 * D + zcol);
        float4 z1 = *reinterpret_cast<const float4*>(g_z + (size_t)s1 * D + zcol);

#define EDGE_ACC4(sv, tv, zv)                                           \
        {                                                               \
            float a0 = sv.x + tv.x, a1 = sv.y + tv.y;                   \
            float a2 = sv.z + tv.z, a3 = sv.w + tv.w;                   \
            a0 = fmaxf(a0, 0.01f * a0); a1 = fmaxf(a1, 0.01f * a1);     \
            a2 = fmaxf(a2, 0.01f * a2); a3 = fmaxf(a3, 0.01f * a3);     \
            acc[0]  += a0 * zv.x; acc[1]  += a0 * zv.y;                 \
            acc[2]  += a0 * zv.z; acc[3]  += a0 * zv.w;                 \
            acc[4]  += a1 * zv.x; acc[5]  += a1 * zv.y;                 \
            acc[6]  += a1 * zv.z; acc[7]  += a1 * zv.w;                 \
            acc[8]  += a2 * zv.x; acc[9]  += a2 * zv.y;                 \
            acc[10] += a2 * zv.z; acc[11] += a2 * zv.w;                 \
            acc[12] += a3 * zv.x; acc[13] += a3 * zv.y;                 \
            acc[14] += a3 * zv.z; acc[15] += a3 * zv.w;                 \
        }
        EDGE_ACC4(sv0, tv0, z0)
        EDGE_ACC4(sv1, tv1, z1)
    }
    if (i < end) {
        unsigned pc = __ldg(&g_csr[i]);
        int s = pc & 0xFFFFu, r = pc >> 16;
        float4 sv = *reinterpret_cast<const float4*>(g_st + (size_t)s * STCOLS + (r << 2));
        float4 tv = *reinterpret_cast<const float4*>(tvb + (r << 2));
        float4 zv = *reinterpret_cast<const float4*>(g_z + (size_t)s * D + zcol);
        EDGE_ACC4(sv, tv, zv)
    }
#undef EDGE_ACC4

    float* o = out + (size_t)w * (H * D) + zcol;
#pragma unroll
    for (int hh = 0; hh < H; hh++) {
        float4* op = reinterpret_cast<float4*>(o + hh * D);
        float4 cur = *op;
        cur.x += acc[hh * 4 + 0];
        cur.y += acc[hh * 4 + 1];
        cur.z += acc[hh * 4 + 2];
        cur.w += acc[hh * 4 + 3];
        *op = cur;
    }
}

// ---------------------------------------------------------------------------
extern "C" void kernel_launch(void* const* d_in, const int* in_sizes, int n_in,
                              void* d_out, int out_size) {
    const float* h_in      = (const float*)d_in[0];
    const float* fc_w      = (const float*)d_in[1];
    const float* self_fc_w = (const float*)d_in[2];
    const float* attn_w    = (const float*)d_in[3];
    const float* w_comp    = (const float*)d_in[4];
    const int*   src       = (const int*)d_in[5];
    const int*   dst       = (const int*)d_in[6];
    const int*   rel       = (const int*)d_in[7];
    float* out = (float*)d_out;

    cudaFuncSetAttribute(tc_gemm1_kernel,
                         cudaFuncAttributeMaxDynamicSharedMemorySize, SM_TOT);
    cudaFuncSetAttribute(tc_gemm2_kernel,
                         cudaFuncAttributeMaxDynamicSharedMemorySize, SM2_TOT);

    build_wst_kernel<<<(D * WSTLD + 255) / 256, 256>>>(w_comp, attn_w);
    build_w1bf16_kernel<<<(W1COLS * INDIM + 255) / 256, 256>>>(fc_w, self_fc_w);

    zero_deg_kernel<<<(NN + 255) / 256, 256>>>();
    hist_kernel<<<(EE / 4 + 255) / 256, 256>>>(dst);
    scan_kernel<<<1, SCAN_T>>>();
    scatter_kernel<<<(EE + 255) / 256, 256>>>(src, dst, rel);

    tc_gemm1_kernel<<<(NN + 127) / 128, 256, SM_TOT>>>(h_in, out);
    tc_gemm2_kernel<<<(NN + 127) / 128, 256, SM2_TOT>>>();

    // two nodes per warp -> NN/2 warps
    aggregate_kernel<<<((NN / 2) * 32 + 255) / 256, 256>>>(out);
}